// round 7
// baseline (speedup 1.0000x reference)
#include <cuda_runtime.h>
#include <math.h>

// ---------------- problem constants ----------------
#define BN   64
#define LN   200
#define BL   12800          // BN*LN
#define DN   256
#define TWO_D 512
#define HN   512
#define G3   1536           // 3*HN
#define QN   1024
#define NQ   1024

// ---------------- device scratch (static, no allocation) ----------------
__device__ float g_x   [BL * TWO_D];   // [12800,512]  GRU input
__device__ float g_xg  [BL * G3];      // [12800,1536] x@w_ih^T + b_ih
__device__ float g_wihT[TWO_D * G3];   // [512,1536]
__device__ float g_whhT[HN * G3];      // [512,1536]
__device__ float g_hbuf[2 * BN * HN];  // ping-pong hidden state
__device__ float g_hall[BL * HN];      // all hidden states [b,t,h]
__device__ float g_M2  [QN * HN];      // matrix @ fc_w
__device__ float g_mb  [QN];           // matrix @ fc_b
__device__ float g_mval[BL];
__device__ int   g_idx [BL];           // q-1
__device__ int   g_qa  [BL];           // answer 0/1
__device__ float g_mc[BL], g_mi[BL], g_nmc[BL], g_aa[BL];
__device__ float g_guess[BN * QN], g_slip[BN * QN];
__device__ float g_preds[BL];

// ---------------- init: zero h0, guess, slip ----------------
__global__ void k_init() {
    int idx = blockIdx.x * blockDim.x + threadIdx.x;
    int stride = gridDim.x * blockDim.x;
    for (int i = idx; i < BN * HN; i += stride) g_hbuf[i] = 0.f;
    for (int i = idx; i < BN * QN; i += stride) { g_guess[i] = 0.f; g_slip[i] = 0.f; }
}

// ---------------- transpose w_ih, w_hh ([1536,512] -> [512,1536]) ----------------
__global__ void k_transpose(const float* __restrict__ w_ih,
                            const float* __restrict__ w_hh) {
    int idx = blockIdx.x * blockDim.x + threadIdx.x;
    int stride = gridDim.x * blockDim.x;
    const int total = G3 * TWO_D;
    for (int i = idx; i < total; i += stride) {
        int r = i / TWO_D;       // gate row 0..1535
        int k = i - r * TWO_D;   // 0..511
        g_wihT[k * G3 + r] = w_ih[i];
        g_whhT[k * G3 + r] = w_hh[i];
    }
}

// ---------------- embeddings -> x ----------------
__global__ void k_embed(const int* __restrict__ qd, const int* __restrict__ qad,
                        const int* __restrict__ pidd,
                        const float* __restrict__ q_emb, const float* __restrict__ qa_emb,
                        const float* __restrict__ q_emb_diff,
                        const float* __restrict__ qa_emb_diff,
                        const float* __restrict__ diff_parm) {
    int bt = blockIdx.x;
    int d  = threadIdx.x;            // 0..255
    int q  = qd[bt];
    int qa = (qad[bt] - q) / NQ;     // 0 or 1
    float pid = diff_parm[pidd[bt]];
    float qe  = q_emb[q * DN + d];
    float qav = qa_emb[qa * DN + d] + qe + pid * qa_emb_diff[qa * DN + d];
    float qv  = qe + pid * q_emb_diff[q * DN + d];
    g_x[bt * TWO_D + d]      = qav;  // qa_embed2
    g_x[bt * TWO_D + DN + d] = qv;   // q_embed2
    if (d == 0) { g_idx[bt] = q - 1; g_qa[bt] = qa; }
}

// ---------------- generic fp32 SGEMM: C[M,N] = A[M,K]*B[K,N] (+bias) ----------------
// BM=BN=64, BK=16, 256 threads, 4x4 microtile. All dims divisible (checked).
__global__ void k_sgemm(const float* __restrict__ A, const float* __restrict__ B,
                        const float* __restrict__ bias, float* __restrict__ C,
                        int M, int N, int K) {
    __shared__ __align__(16) float As[16][64];
    __shared__ __align__(16) float Bs[16][64];
    int tid = threadIdx.x;
    int n0 = blockIdx.x * 64;
    int m0 = blockIdx.y * 64;
    int tx = tid & 15;        // 0..15 (N dir)
    int ty = tid >> 4;        // 0..15 (M dir)
    int arow = tid >> 2;            // 0..63
    int aoff = (tid & 3) * 4;       // 0,4,8,12
    int brow = tid >> 4;            // 0..15
    int boff = (tid & 15) * 4;      // 0..60

    float c[4][4] = {};
    for (int k0 = 0; k0 < K; k0 += 16) {
        float4 a4 = *(const float4*)&A[(m0 + arow) * K + k0 + aoff];
        As[aoff + 0][arow] = a4.x;
        As[aoff + 1][arow] = a4.y;
        As[aoff + 2][arow] = a4.z;
        As[aoff + 3][arow] = a4.w;
        *(float4*)&Bs[brow][boff] = *(const float4*)&B[(k0 + brow) * N + n0 + boff];
        __syncthreads();
#pragma unroll
        for (int kk = 0; kk < 16; kk++) {
            float4 av = *(float4*)&As[kk][ty * 4];
            float4 bv = *(float4*)&Bs[kk][tx * 4];
            c[0][0] = fmaf(av.x, bv.x, c[0][0]); c[0][1] = fmaf(av.x, bv.y, c[0][1]);
            c[0][2] = fmaf(av.x, bv.z, c[0][2]); c[0][3] = fmaf(av.x, bv.w, c[0][3]);
            c[1][0] = fmaf(av.y, bv.x, c[1][0]); c[1][1] = fmaf(av.y, bv.y, c[1][1]);
            c[1][2] = fmaf(av.y, bv.z, c[1][2]); c[1][3] = fmaf(av.y, bv.w, c[1][3]);
            c[2][0] = fmaf(av.z, bv.x, c[2][0]); c[2][1] = fmaf(av.z, bv.y, c[2][1]);
            c[2][2] = fmaf(av.z, bv.z, c[2][2]); c[2][3] = fmaf(av.z, bv.w, c[2][3]);
            c[3][0] = fmaf(av.w, bv.x, c[3][0]); c[3][1] = fmaf(av.w, bv.y, c[3][1]);
            c[3][2] = fmaf(av.w, bv.z, c[3][2]); c[3][3] = fmaf(av.w, bv.w, c[3][3]);
        }
        __syncthreads();
    }
    int col = n0 + tx * 4;
    float4 bb = bias ? *(const float4*)&bias[col] : make_float4(0.f, 0.f, 0.f, 0.f);
#pragma unroll
    for (int i = 0; i < 4; i++) {
        float4 v;
        v.x = c[i][0] + bb.x; v.y = c[i][1] + bb.y;
        v.z = c[i][2] + bb.z; v.w = c[i][3] + bb.w;
        *(float4*)&C[(m0 + ty * 4 + i) * N + col] = v;
    }
}

// ---------------- mb[i] = matrix[i,:] . fc_b ----------------
__global__ void k_mb(const float* __restrict__ matrix, const float* __restrict__ fc_b) {
    int warp = threadIdx.x >> 5, lane = threadIdx.x & 31;
    int i = blockIdx.x * 8 + warp;
    float s = 0.f;
    for (int q = lane; q < QN; q += 32) s = fmaf(matrix[i * QN + q], fc_b[q], s);
#pragma unroll
    for (int o = 16; o; o >>= 1) s += __shfl_down_sync(0xffffffffu, s, o);
    if (lane == 0) g_mb[i] = s;
}

// ---------------- one GRU step ----------------
// 128 blocks x 256 threads. Block owns hidden units j0..j0+3 (j0 = 4*blockIdx)
// for ALL 64 batches. Thread = (batch b = tid>>2, jj = tid&3).
// w_hh rows {j, 512+j, 1024+j} staged in bank-padded smem (pitch 520 floats).
__global__ void k_gru_step(const float* __restrict__ b_hh, int t) {
    __shared__ __align__(16) float ws[12 * 520];
    int tid = threadIdx.x;
    int j0 = blockIdx.x * 4;

    // stage weights: ws[c][k] = w_hh[g*512 + j0 + jj][k],  c = g*4+jj
    for (int idx = tid; idx < 512 * 12; idx += 256) {
        int k = idx / 12;
        int c = idx - k * 12;
        int g = c >> 2, jj = c & 3;
        ws[c * 520 + k] = g_whhT[k * G3 + g * HN + j0 + jj];
    }
    __syncthreads();

    int b = tid >> 2, jj = tid & 3;
    const float* h_in = g_hbuf + (t & 1) * BN * HN;
    const float4* hb = (const float4*)(h_in + b * HN);
    const float4* wr = (const float4*)(ws + (0 + jj) * 520);
    const float4* wz = (const float4*)(ws + (4 + jj) * 520);
    const float4* wn = (const float4*)(ws + (8 + jj) * 520);

    float ar = 0.f, az = 0.f, an = 0.f;
#pragma unroll 4
    for (int k4 = 0; k4 < 128; k4++) {
        float4 h4 = hb[k4];
        float4 a = wr[k4];
        float4 z4 = wz[k4];
        float4 n4 = wn[k4];
        ar = fmaf(a.x, h4.x, ar);  ar = fmaf(a.y, h4.y, ar);
        ar = fmaf(a.z, h4.z, ar);  ar = fmaf(a.w, h4.w, ar);
        az = fmaf(z4.x, h4.x, az); az = fmaf(z4.y, h4.y, az);
        az = fmaf(z4.z, h4.z, az); az = fmaf(z4.w, h4.w, az);
        an = fmaf(n4.x, h4.x, an); an = fmaf(n4.y, h4.y, an);
        an = fmaf(n4.z, h4.z, an); an = fmaf(n4.w, h4.w, an);
    }

    int j = j0 + jj;
    int bt = b * LN + t;
    const float* xgp = g_xg + bt * G3;
    float xr = xgp[j], xz = xgp[HN + j], xn = xgp[2 * HN + j];
    float hr = ar + b_hh[j];
    float hz = az + b_hh[HN + j];
    float hn = an + b_hh[2 * HN + j];
    float r = 1.f / (1.f + expf(-(xr + hr)));
    float z = 1.f / (1.f + expf(-(xz + hz)));
    float n = tanhf(xn + r * hn);
    float hold = h_in[b * HN + j];
    float hnew = (1.f - z) * n + z * hold;
    float* h_out = g_hbuf + ((t + 1) & 1) * BN * HN;
    h_out[b * HN + j] = hnew;
    g_hall[bt * HN + j] = hnew;
}

// ---------------- mval[b,t] = threshold( h[b,t,:] . M2[idx,:] + mb[idx] ) ----------------
__global__ void k_mval() {
    int warp = threadIdx.x >> 5, lane = threadIdx.x & 31;
    int bt = blockIdx.x * 8 + warp;
    int i = g_idx[bt];
    const float* hp = g_hall + bt * HN;
    const float* m2 = g_M2 + i * HN;
    float s = 0.f;
#pragma unroll 4
    for (int k = lane; k < HN; k += 32) s = fmaf(hp[k], m2[k], s);
#pragma unroll
    for (int o = 16; o; o >>= 1) s += __shfl_down_sync(0xffffffffu, s, o);
    if (lane == 0) {
        float v = s + g_mb[i];
        g_mval[bt] = (v >= 0.4f) ? 1.0f : v;
    }
}

// ---------------- same-question history counters ----------------
__global__ void k_counts(const int* __restrict__ qd) {
    __shared__ int   qs[LN];
    __shared__ float a1m[LN], a0m[LN], a0n[LN];
    int b = blockIdx.x;
    int tid = threadIdx.x;
    if (tid < LN) {
        int bt = b * LN + tid;
        int q = qd[bt];
        float m = g_mval[bt];
        int qa = g_qa[bt];
        float mast = (m == 1.0f) ? 1.f : 0.f;
        float notm = (m == 0.0f) ? 1.f : 0.f;
        qs[tid]  = q;
        a1m[tid] = (qa == 1) ? mast : 0.f;  // qa1 * mast
        a0m[tid] = (qa == 0) ? mast : 0.f;  // qa0 * mast
        a0n[tid] = (qa == 0) ? notm : 0.f;  // qa0 * notm
    }
    __syncthreads();
    if (tid < LN) {
        int qt = qs[tid];
        float mc = 0.f, mi = 0.f, nmc = 0.f;
        int cnt = 1;                          // k == t always matches (tri_incl)
        for (int k = 0; k < tid; k++) {
            if (qs[k] == qt) { mc += a1m[k]; mi += a0m[k]; nmc += a0n[k]; cnt++; }
        }
        int bt = b * LN + tid;
        g_mc[bt] = mc; g_mi[bt] = mi; g_nmc[bt] = nmc; g_aa[bt] = (float)cnt;
    }
}

// ---------------- sequential DINA scan (thread per batch) ----------------
__global__ void k_dina() {
    int b = threadIdx.x;
    if (b >= BN) return;
    for (int t = 0; t < LN; t++) {
        int bt = b * LN + t;
        int i = g_idx[bt];
        float m = g_mval[bt];
        int qa = g_qa[bt];
        float aa = g_aa[bt];
        float gu;
        if (m == 1.0f)       gu = g_mc[bt] / aa;
        else if (qa == 0)    gu = 1.0f - g_nmc[bt] / aa;
        else                 gu = g_nmc[bt] / aa;
        bool us = (m == 1.0f) && (qa == 0);
        float og = g_guess[b * QN + i];
        float os = g_slip[b * QN + i];
        float ng = us ? og : gu;
        float ns = us ? (g_mi[bt] / aa) : os;
        g_guess[b * QN + i] = ng;
        g_slip[b * QN + i] = ns;
        float p = (1.f - ns) * (m * ng + (1.f - ns) * (1.f - m));
        g_preds[bt] = p;
    }
}

// ---------------- final: sigmoid, masked MSE + c_reg, mask count (deterministic) ----------------
__global__ void k_final(const float* __restrict__ target, const int* __restrict__ pidd,
                        const float* __restrict__ diff_parm, float* __restrict__ out,
                        int out_size) {
    __shared__ double sm[256];
    __shared__ double sc[256];
    __shared__ int    si[256];
    int tid = threadIdx.x;
    int poff = (out_size >= BL + 2) ? 1 : 0;
    double mse = 0.0, cr = 0.0;
    int cnt = 0;
    for (int i = tid; i < BL; i += 256) {
        float p = g_preds[i];
        if (poff + i < out_size) out[poff + i] = 1.f / (1.f + expf(-p));
        float lab = target[i];
        if (lab > -0.9f) { double d = (double)p - (double)lab; mse += d * d; cnt++; }
        float pe = diff_parm[pidd[i]];
        cr += (double)pe * (double)pe;
    }
    sm[tid] = mse; sc[tid] = cr; si[tid] = cnt;
    __syncthreads();
    for (int o = 128; o; o >>= 1) {
        if (tid < o) { sm[tid] += sm[tid + o]; sc[tid] += sc[tid + o]; si[tid] += si[tid + o]; }
        __syncthreads();
    }
    if (tid == 0) {
        float loss = (float)(sm[0] + sc[0] * 1e-5);
        if (out_size >= BL + 2) {
            out[0] = loss;
            out[BL + 1] = (float)si[0];
        } else if (out_size == 1) {
            out[0] = loss;
        }
    }
}

// ---------------- launch ----------------
extern "C" void kernel_launch(void* const* d_in, const int* in_sizes, int n_in,
                              void* d_out, int out_size) {
    const int*   qd          = (const int*)  d_in[0];
    const int*   qad         = (const int*)  d_in[1];
    const int*   pidd        = (const int*)  d_in[2];
    const float* matrix      = (const float*)d_in[3];
    const float* target      = (const float*)d_in[4];
    const float* q_emb       = (const float*)d_in[5];
    const float* qa_emb      = (const float*)d_in[6];
    const float* q_emb_diff  = (const float*)d_in[7];
    const float* qa_emb_diff = (const float*)d_in[8];
    const float* diff_parm   = (const float*)d_in[9];
    const float* w_ih        = (const float*)d_in[10];
    const float* w_hh        = (const float*)d_in[11];
    const float* b_ih        = (const float*)d_in[12];
    const float* b_hh        = (const float*)d_in[13];
    const float* fc_w        = (const float*)d_in[14];
    const float* fc_b        = (const float*)d_in[15];
    float* out = (float*)d_out;

    // resolve scratch symbol addresses (host API, not a stream op — capture-safe)
    float *px, *pxg, *pwihT, *pM2;
    cudaGetSymbolAddress((void**)&px,    g_x);
    cudaGetSymbolAddress((void**)&pxg,   g_xg);
    cudaGetSymbolAddress((void**)&pwihT, g_wihT);
    cudaGetSymbolAddress((void**)&pM2,   g_M2);

    k_init<<<64, 256>>>();
    k_transpose<<<256, 256>>>(w_ih, w_hh);
    k_embed<<<BL, 256>>>(qd, qad, pidd, q_emb, qa_emb, q_emb_diff, qa_emb_diff, diff_parm);

    // xg = x @ w_ih^T + b_ih : M=12800, N=1536, K=512
    k_sgemm<<<dim3(G3 / 64, BL / 64), 256>>>(px, pwihT, b_ih, pxg, BL, G3, TWO_D);
    // M2 = matrix @ fc_w : M=1024, N=512, K=1024
    k_sgemm<<<dim3(HN / 64, QN / 64), 256>>>(matrix, fc_w, nullptr, pM2, QN, HN, QN);
    k_mb<<<128, 256>>>(matrix, fc_b);

    for (int t = 0; t < LN; t++)
        k_gru_step<<<128, 256>>>(b_hh, t);

    k_mval<<<BL / 8, 256>>>();
    k_counts<<<BN, 256>>>(qd);
    k_dina<<<1, 64>>>();
    k_final<<<1, 256>>>(target, pidd, diff_parm, out, out_size);
}

// round 11
// speedup vs baseline: 1.1548x; 1.1548x over previous
#include <cuda_runtime.h>
#include <math.h>

// ---------------- problem constants ----------------
#define BN   64
#define LN   200
#define BL   12800          // BN*LN
#define DN   256
#define TWO_D 512
#define HN   512
#define G3   1536           // 3*HN
#define QN   1024
#define NQ   1024
#define NBLK 128            // persistent GRU blocks (<=148 SMs, all resident)

typedef unsigned long long ull;

// ---------------- f32x2 packed-math helpers (sm_100+) ----------------
__device__ __forceinline__ ull dup2(float x) {
    ull r; asm("mov.b64 %0, {%1, %1};" : "=l"(r) : "f"(x)); return r;
}
__device__ __forceinline__ ull ffma2(ull a, ull b, ull c) {
    ull d; asm("fma.rn.f32x2 %0, %1, %2, %3;" : "=l"(d) : "l"(a), "l"(b), "l"(c)); return d;
}
__device__ __forceinline__ float2 unpk(ull v) {
    float2 f; asm("mov.b64 {%0, %1}, %2;" : "=f"(f.x), "=f"(f.y) : "l"(v)); return f;
}

// ---------------- device scratch (static, no allocation) ----------------
__device__ float g_x   [BL * TWO_D];   // [12800,512]  GRU input
__device__ float g_xg  [BL * G3];      // [12800,1536] x@w_ih^T + b_ih
__device__ float g_wihT[TWO_D * G3];   // [512,1536]
__device__ float g_whhT[HN * G3];      // [512,1536]
__device__ float g_hbuf[2 * BN * HN];  // ping-pong hidden state
__device__ float g_hall[BL * HN];      // all hidden states [b,t,h]
__device__ float g_M2  [QN * HN];      // matrix @ fc_w
__device__ float g_mb  [QN];           // matrix @ fc_b
__device__ float g_mval[BL];
__device__ int   g_idx [BL];           // q-1
__device__ int   g_qa  [BL];           // answer 0/1
__device__ float g_mc[BL], g_mi[BL], g_nmc[BL], g_aa[BL];
__device__ float g_guess[BN * QN], g_slip[BN * QN];
__device__ float g_preds[BL];
__device__ unsigned int g_bar_count;   // monotonic grid-barrier arrival counter

// ---------------- init: zero h0, guess, slip, barrier ----------------
__global__ void k_init() {
    int idx = blockIdx.x * blockDim.x + threadIdx.x;
    int stride = gridDim.x * blockDim.x;
    if (idx == 0) g_bar_count = 0u;
    for (int i = idx; i < BN * HN; i += stride) g_hbuf[i] = 0.f;
    for (int i = idx; i < BN * QN; i += stride) { g_guess[i] = 0.f; g_slip[i] = 0.f; }
}

// ---------------- transpose w_ih, w_hh ([1536,512] -> [512,1536]) ----------------
__global__ void k_transpose(const float* __restrict__ w_ih,
                            const float* __restrict__ w_hh) {
    int idx = blockIdx.x * blockDim.x + threadIdx.x;
    int stride = gridDim.x * blockDim.x;
    const int total = G3 * TWO_D;
    for (int i = idx; i < total; i += stride) {
        int r = i / TWO_D;       // gate row 0..1535
        int k = i - r * TWO_D;   // 0..511
        g_wihT[k * G3 + r] = w_ih[i];
        g_whhT[k * G3 + r] = w_hh[i];
    }
}

// ---------------- embeddings -> x ----------------
__global__ void k_embed(const int* __restrict__ qd, const int* __restrict__ qad,
                        const int* __restrict__ pidd,
                        const float* __restrict__ q_emb, const float* __restrict__ qa_emb,
                        const float* __restrict__ q_emb_diff,
                        const float* __restrict__ qa_emb_diff,
                        const float* __restrict__ diff_parm) {
    int bt = blockIdx.x;
    int d  = threadIdx.x;            // 0..255
    int q  = qd[bt];
    int qa = (qad[bt] - q) / NQ;     // 0 or 1
    float pid = diff_parm[pidd[bt]];
    float qe  = q_emb[q * DN + d];
    float qav = qa_emb[qa * DN + d] + qe + pid * qa_emb_diff[qa * DN + d];
    float qv  = qe + pid * q_emb_diff[q * DN + d];
    g_x[bt * TWO_D + d]      = qav;  // qa_embed2
    g_x[bt * TWO_D + DN + d] = qv;   // q_embed2
    if (d == 0) { g_idx[bt] = q - 1; g_qa[bt] = qa; }
}

// ---------------- fp32 SGEMM with f32x2 packed FMA ----------------
// C[M,N] = A[M,K]*B[K,N] (+bias). 64x64 tile, BK=16, 256 thr, 4x4 microtile.
// Adjacent N-outputs packed in one f32x2 lane pair: each scalar output's
// FMA sequence is bit-identical to the scalar version.
__global__ void k_sgemm(const float* __restrict__ A, const float* __restrict__ B,
                        const float* __restrict__ bias, float* __restrict__ C,
                        int M, int N, int K) {
    __shared__ __align__(16) float As[16][64];
    __shared__ __align__(16) float Bs[16][64];
    int tid = threadIdx.x;
    int n0 = blockIdx.x * 64;
    int m0 = blockIdx.y * 64;
    int tx = tid & 15;        // N dir
    int ty = tid >> 4;        // M dir
    int arow = tid >> 2;            // 0..63
    int aoff = (tid & 3) * 4;       // 0,4,8,12
    int brow = tid >> 4;            // 0..15
    int boff = (tid & 15) * 4;      // 0..60

    ull c2[4][2] = {};
    for (int k0 = 0; k0 < K; k0 += 16) {
        float4 a4 = *(const float4*)&A[(m0 + arow) * K + k0 + aoff];
        As[aoff + 0][arow] = a4.x;
        As[aoff + 1][arow] = a4.y;
        As[aoff + 2][arow] = a4.z;
        As[aoff + 3][arow] = a4.w;
        *(float4*)&Bs[brow][boff] = *(const float4*)&B[(k0 + brow) * N + n0 + boff];
        __syncthreads();
#pragma unroll
        for (int kk = 0; kk < 16; kk++) {
            float4 av = *(const float4*)&As[kk][ty * 4];
            ulonglong2 bv = *(const ulonglong2*)&Bs[kk][tx * 4];
            ull a0 = dup2(av.x), a1 = dup2(av.y), a2 = dup2(av.z), a3 = dup2(av.w);
            c2[0][0] = ffma2(a0, bv.x, c2[0][0]); c2[0][1] = ffma2(a0, bv.y, c2[0][1]);
            c2[1][0] = ffma2(a1, bv.x, c2[1][0]); c2[1][1] = ffma2(a1, bv.y, c2[1][1]);
            c2[2][0] = ffma2(a2, bv.x, c2[2][0]); c2[2][1] = ffma2(a2, bv.y, c2[2][1]);
            c2[3][0] = ffma2(a3, bv.x, c2[3][0]); c2[3][1] = ffma2(a3, bv.y, c2[3][1]);
        }
        __syncthreads();
    }
    int col = n0 + tx * 4;
    float4 bb = bias ? *(const float4*)&bias[col] : make_float4(0.f, 0.f, 0.f, 0.f);
#pragma unroll
    for (int i = 0; i < 4; i++) {
        float2 lo = unpk(c2[i][0]);
        float2 hi = unpk(c2[i][1]);
        float4 v;
        v.x = lo.x + bb.x; v.y = lo.y + bb.y;
        v.z = hi.x + bb.z; v.w = hi.y + bb.w;
        *(float4*)&C[(m0 + ty * 4 + i) * N + col] = v;
    }
}

// ---------------- mb[i] = matrix[i,:] . fc_b ----------------
__global__ void k_mb(const float* __restrict__ matrix, const float* __restrict__ fc_b) {
    int warp = threadIdx.x >> 5, lane = threadIdx.x & 31;
    int i = blockIdx.x * 8 + warp;
    float s = 0.f;
    for (int q = lane; q < QN; q += 32) s = fmaf(matrix[i * QN + q], fc_b[q], s);
#pragma unroll
    for (int o = 16; o; o >>= 1) s += __shfl_down_sync(0xffffffffu, s, o);
    if (lane == 0) g_mb[i] = s;
}

// ---------------- persistent GRU scan ----------------
// One launch. 128 blocks x 256 threads, all resident. Block owns hidden units
// j0..j0+3 for ALL 64 batches; thread = (batch b = tid>>2, jj = tid&3).
// Weights staged in smem ONCE: (r,z) rows interleaved as f32x2 pairs, n rows
// separate. Grid barrier (monotonic atomic count) between steps.
__global__ void __launch_bounds__(256) k_gru_all(const float* __restrict__ b_hh) {
    // pitches chosen for 16B alignment + 8-bank offset per jj (conflict-free)
    __shared__ __align__(16) float ws_rz[4][1032];  // [jj][2k]=(r), [2k+1]=(z)
    __shared__ __align__(16) float ws_n [4][520];
    int tid = threadIdx.x;
    int j0 = blockIdx.x * 4;

    for (int idx = tid; idx < 512 * 4; idx += 256) {
        int k  = idx >> 2;
        int jj = idx & 3;
        const float* base = g_whhT + k * G3 + j0 + jj;
        ws_rz[jj][2 * k]     = base[0];        // w_hh row j        (r gate)
        ws_rz[jj][2 * k + 1] = base[HN];       // w_hh row 512+j    (z gate)
        ws_n [jj][k]         = base[2 * HN];   // w_hh row 1024+j   (n gate)
    }

    int b = tid >> 2, jj = tid & 3;
    int j = j0 + jj;
    float bhr = b_hh[j], bhz = b_hh[HN + j], bhn = b_hh[2 * HN + j];
    const ulonglong2* wrz2 = (const ulonglong2*)&ws_rz[jj][0];
    const float4*     wn4  = (const float4*)&ws_n[jj][0];
    __syncthreads();

    unsigned int bar_target = 0;
    for (int t = 0; t < LN; t++) {
        const float* h_in = g_hbuf + (t & 1) * BN * HN + b * HN;
        const float4* hb = (const float4*)h_in;

        ull arz = 0ULL;       // packed (ar, az)
        float an = 0.f;
#pragma unroll 4
        for (int k4 = 0; k4 < 128; k4++) {
            float4 h4 = hb[k4];
            ulonglong2 wA = wrz2[2 * k4];
            ulonglong2 wB = wrz2[2 * k4 + 1];
            float4 n4 = wn4[k4];
            arz = ffma2(wA.x, dup2(h4.x), arz);
            arz = ffma2(wA.y, dup2(h4.y), arz);
            arz = ffma2(wB.x, dup2(h4.z), arz);
            arz = ffma2(wB.y, dup2(h4.w), arz);
            an = fmaf(n4.x, h4.x, an); an = fmaf(n4.y, h4.y, an);
            an = fmaf(n4.z, h4.z, an); an = fmaf(n4.w, h4.w, an);
        }
        float2 rzv = unpk(arz);

        int bt = b * LN + t;
        const float* xgp = g_xg + (size_t)bt * G3;
        float hr = rzv.x + bhr;
        float hz = rzv.y + bhz;
        float hn = an + bhn;
        float r = 1.f / (1.f + expf(-(xgp[j] + hr)));
        float z = 1.f / (1.f + expf(-(xgp[HN + j] + hz)));
        float n = tanhf(xgp[2 * HN + j] + r * hn);
        float hold = h_in[j];
        float hnew = (1.f - z) * n + z * hold;
        g_hbuf[((t + 1) & 1) * BN * HN + b * HN + j] = hnew;
        g_hall[(size_t)bt * HN + j] = hnew;

        // ---- grid barrier (monotonic count; reset each launch by k_init) ----
        bar_target += NBLK;
        __syncthreads();
        if (tid == 0) {
            __threadfence();
            atomicAdd(&g_bar_count, 1u);
            while (atomicAdd(&g_bar_count, 0u) < bar_target) {
                __nanosleep(32);
            }
            __threadfence();
        }
        __syncthreads();
    }
}

// ---------------- mval[b,t] = threshold( h[b,t,:] . M2[idx,:] + mb[idx] ) ----------------
__global__ void k_mval() {
    int warp = threadIdx.x >> 5, lane = threadIdx.x & 31;
    int bt = blockIdx.x * 8 + warp;
    int i = g_idx[bt];
    const float* hp = g_hall + (size_t)bt * HN;
    const float* m2 = g_M2 + i * HN;
    float s = 0.f;
#pragma unroll 4
    for (int k = lane; k < HN; k += 32) s = fmaf(hp[k], m2[k], s);
#pragma unroll
    for (int o = 16; o; o >>= 1) s += __shfl_down_sync(0xffffffffu, s, o);
    if (lane == 0) {
        float v = s + g_mb[i];
        g_mval[bt] = (v >= 0.4f) ? 1.0f : v;
    }
}

// ---------------- same-question history counters ----------------
__global__ void k_counts(const int* __restrict__ qd) {
    __shared__ int   qs[LN];
    __shared__ float a1m[LN], a0m[LN], a0n[LN];
    int b = blockIdx.x;
    int tid = threadIdx.x;
    if (tid < LN) {
        int bt = b * LN + tid;
        int q = qd[bt];
        float m = g_mval[bt];
        int qa = g_qa[bt];
        float mast = (m == 1.0f) ? 1.f : 0.f;
        float notm = (m == 0.0f) ? 1.f : 0.f;
        qs[tid]  = q;
        a1m[tid] = (qa == 1) ? mast : 0.f;
        a0m[tid] = (qa == 0) ? mast : 0.f;
        a0n[tid] = (qa == 0) ? notm : 0.f;
    }
    __syncthreads();
    if (tid < LN) {
        int qt = qs[tid];
        float mc = 0.f, mi = 0.f, nmc = 0.f;
        int cnt = 1;                          // k == t always matches (tri_incl)
        for (int k = 0; k < tid; k++) {
            if (qs[k] == qt) { mc += a1m[k]; mi += a0m[k]; nmc += a0n[k]; cnt++; }
        }
        int bt = b * LN + tid;
        g_mc[bt] = mc; g_mi[bt] = mi; g_nmc[bt] = nmc; g_aa[bt] = (float)cnt;
    }
}

// ---------------- sequential DINA scan (thread per batch) ----------------
__global__ void k_dina() {
    int b = threadIdx.x;
    if (b >= BN) return;
    for (int t = 0; t < LN; t++) {
        int bt = b * LN + t;
        int i = g_idx[bt];
        float m = g_mval[bt];
        int qa = g_qa[bt];
        float aa = g_aa[bt];
        float gu;
        if (m == 1.0f)       gu = g_mc[bt] / aa;
        else if (qa == 0)    gu = 1.0f - g_nmc[bt] / aa;
        else                 gu = g_nmc[bt] / aa;
        bool us = (m == 1.0f) && (qa == 0);
        float og = g_guess[b * QN + i];
        float os = g_slip[b * QN + i];
        float ng = us ? og : gu;
        float ns = us ? (g_mi[bt] / aa) : os;
        g_guess[b * QN + i] = ng;
        g_slip[b * QN + i] = ns;
        float p = (1.f - ns) * (m * ng + (1.f - ns) * (1.f - m));
        g_preds[bt] = p;
    }
}

// ---------------- final: sigmoid, masked MSE + c_reg, mask count ----------------
__global__ void k_final(const float* __restrict__ target, const int* __restrict__ pidd,
                        const float* __restrict__ diff_parm, float* __restrict__ out,
                        int out_size) {
    __shared__ double sm[256];
    __shared__ double sc[256];
    __shared__ int    si[256];
    int tid = threadIdx.x;
    int poff = (out_size >= BL + 2) ? 1 : 0;
    double mse = 0.0, cr = 0.0;
    int cnt = 0;
    for (int i = tid; i < BL; i += 256) {
        float p = g_preds[i];
        if (poff + i < out_size) out[poff + i] = 1.f / (1.f + expf(-p));
        float lab = target[i];
        if (lab > -0.9f) { double d = (double)p - (double)lab; mse += d * d; cnt++; }
        float pe = diff_parm[pidd[i]];
        cr += (double)pe * (double)pe;
    }
    sm[tid] = mse; sc[tid] = cr; si[tid] = cnt;
    __syncthreads();
    for (int o = 128; o; o >>= 1) {
        if (tid < o) { sm[tid] += sm[tid + o]; sc[tid] += sc[tid + o]; si[tid] += si[tid + o]; }
        __syncthreads();
    }
    if (tid == 0) {
        float loss = (float)(sm[0] + sc[0] * 1e-5);
        if (out_size >= BL + 2) {
            out[0] = loss;
            out[BL + 1] = (float)si[0];
        } else if (out_size == 1) {
            out[0] = loss;
        }
    }
}

// ---------------- launch ----------------
extern "C" void kernel_launch(void* const* d_in, const int* in_sizes, int n_in,
                              void* d_out, int out_size) {
    const int*   qd          = (const int*)  d_in[0];
    const int*   qad         = (const int*)  d_in[1];
    const int*   pidd        = (const int*)  d_in[2];
    const float* matrix      = (const float*)d_in[3];
    const float* target      = (const float*)d_in[4];
    const float* q_emb       = (const float*)d_in[5];
    const float* qa_emb      = (const float*)d_in[6];
    const float* q_emb_diff  = (const float*)d_in[7];
    const float* qa_emb_diff = (const float*)d_in[8];
    const float* diff_parm   = (const float*)d_in[9];
    const float* w_ih        = (const float*)d_in[10];
    const float* w_hh        = (const float*)d_in[11];
    const float* b_ih        = (const float*)d_in[12];
    const float* b_hh        = (const float*)d_in[13];
    const float* fc_w        = (const float*)d_in[14];
    const float* fc_b        = (const float*)d_in[15];
    float* out = (float*)d_out;

    float *px, *pxg, *pwihT, *pM2;
    cudaGetSymbolAddress((void**)&px,    g_x);
    cudaGetSymbolAddress((void**)&pxg,   g_xg);
    cudaGetSymbolAddress((void**)&pwihT, g_wihT);
    cudaGetSymbolAddress((void**)&pM2,   g_M2);

    k_init<<<64, 256>>>();
    k_transpose<<<256, 256>>>(w_ih, w_hh);
    k_embed<<<BL, 256>>>(qd, qad, pidd, q_emb, qa_emb, q_emb_diff, qa_emb_diff, diff_parm);

    // xg = x @ w_ih^T + b_ih : M=12800, N=1536, K=512
    k_sgemm<<<dim3(G3 / 64, BL / 64), 256>>>(px, pwihT, b_ih, pxg, BL, G3, TWO_D);
    // M2 = matrix @ fc_w : M=1024, N=512, K=1024
    k_sgemm<<<dim3(HN / 64, QN / 64), 256>>>(matrix, fc_w, nullptr, pM2, QN, HN, QN);
    k_mb<<<128, 256>>>(matrix, fc_b);

    // persistent GRU scan: one launch for all 200 steps
    k_gru_all<<<NBLK, 256>>>(b_hh);

    k_mval<<<BL / 8, 256>>>();
    k_counts<<<BN, 256>>>(qd);
    k_dina<<<1, 64>>>();
    k_final<<<1, 256>>>(target, pidd, diff_parm, out, out_size);
}

// round 14
// speedup vs baseline: 1.3442x; 1.1640x over previous
#include <cuda_runtime.h>
#include <math.h>

// ---------------- problem constants ----------------
#define BN   64
#define LN   200
#define BL   12800          // BN*LN
#define DN   256
#define TWO_D 512
#define HN   512
#define G3   1536           // 3*HN
#define QN   1024
#define NQ   1024
#define NBLK 128            // persistent GRU blocks (1/SM, <=148 SMs, all resident)

typedef unsigned long long ull;

// ---------------- f32x2 packed-math helpers (sm_100+) ----------------
__device__ __forceinline__ ull dup2(float x) {
    ull r; asm("mov.b64 %0, {%1, %1};" : "=l"(r) : "f"(x)); return r;
}
__device__ __forceinline__ ull ffma2(ull a, ull b, ull c) {
    ull d; asm("fma.rn.f32x2 %0, %1, %2, %3;" : "=l"(d) : "l"(a), "l"(b), "l"(c)); return d;
}
__device__ __forceinline__ float2 unpk(ull v) {
    float2 f; asm("mov.b64 {%0, %1}, %2;" : "=f"(f.x), "=f"(f.y) : "l"(v)); return f;
}
__device__ __forceinline__ void cpa16(unsigned int s, const void* g) {
    asm volatile("cp.async.cg.shared.global [%0], [%1], 16;" :: "r"(s), "l"(g) : "memory");
}

// ---------------- device scratch (static, no allocation) ----------------
__device__ float g_x   [BL * TWO_D];   // [12800,512]  GRU input
__device__ float g_xg  [BL * G3];      // [12800,1536] x@w_ih^T + b_ih
__device__ float g_wihT[TWO_D * G3];   // [512,1536]
__device__ float g_whhT[HN * G3];      // [512,1536]
__device__ float g_hall[BL * HN];      // all hidden states [b,t,h]
__device__ float g_M2  [QN * HN];      // matrix @ fc_w
__device__ float g_mb  [QN];           // matrix @ fc_b
__device__ float g_mval[BL];
__device__ int   g_idx [BL];           // q-1
__device__ int   g_qa  [BL];           // answer 0/1
__device__ float g_preds[BL];
__device__ unsigned int g_bar_count;   // monotonic grid-barrier arrival counter

// ---------------- init: reset barrier counter ----------------
__global__ void k_init() {
    if (threadIdx.x == 0 && blockIdx.x == 0) g_bar_count = 0u;
}

// ---------------- transpose w_ih, w_hh ([1536,512] -> [512,1536]) ----------------
__global__ void k_transpose(const float* __restrict__ w_ih,
                            const float* __restrict__ w_hh) {
    int idx = blockIdx.x * blockDim.x + threadIdx.x;
    int stride = gridDim.x * blockDim.x;
    const int total = G3 * TWO_D;
    for (int i = idx; i < total; i += stride) {
        int r = i / TWO_D;       // gate row 0..1535
        int k = i - r * TWO_D;   // 0..511
        g_wihT[k * G3 + r] = w_ih[i];
        g_whhT[k * G3 + r] = w_hh[i];
    }
}

// ---------------- embeddings -> x ----------------
__global__ void k_embed(const int* __restrict__ qd, const int* __restrict__ qad,
                        const int* __restrict__ pidd,
                        const float* __restrict__ q_emb, const float* __restrict__ qa_emb,
                        const float* __restrict__ q_emb_diff,
                        const float* __restrict__ qa_emb_diff,
                        const float* __restrict__ diff_parm) {
    int bt = blockIdx.x;
    int d  = threadIdx.x;            // 0..255
    int q  = qd[bt];
    int qa = (qad[bt] - q) / NQ;     // 0 or 1
    float pid = diff_parm[pidd[bt]];
    float qe  = q_emb[q * DN + d];
    float qav = qa_emb[qa * DN + d] + qe + pid * qa_emb_diff[qa * DN + d];
    float qv  = qe + pid * q_emb_diff[q * DN + d];
    g_x[bt * TWO_D + d]      = qav;  // qa_embed2
    g_x[bt * TWO_D + DN + d] = qv;   // q_embed2
    if (d == 0) { g_idx[bt] = q - 1; g_qa[bt] = qa; }
}

// ---------------- fp32 SGEMM, f32x2 packed, 64Mx128N tile, 4x8 microtile ----------------
__global__ void __launch_bounds__(256) k_sgemm(
        const float* __restrict__ A, const float* __restrict__ B,
        const float* __restrict__ bias, float* __restrict__ C,
        int M, int N, int K) {
    __shared__ __align__(16) float As[16][64];
    __shared__ __align__(16) float Bs[16][128];
    int tid = threadIdx.x;
    int n0 = blockIdx.x * 128;
    int m0 = blockIdx.y * 64;
    int tx = tid & 15;        // N dir, 8 cols each
    int ty = tid >> 4;        // M dir, 4 rows each
    int arow = tid >> 2;            // 0..63
    int aoff = (tid & 3) * 4;       // 0,4,8,12
    int brow = (tid >> 5) * 2;      // 0,2,..,14
    int bcol = (tid & 31) * 4;      // 0..124

    ull c2[4][4] = {};
    for (int k0 = 0; k0 < K; k0 += 16) {
        float4 a4 = *(const float4*)&A[(m0 + arow) * K + k0 + aoff];
        As[aoff + 0][arow] = a4.x;
        As[aoff + 1][arow] = a4.y;
        As[aoff + 2][arow] = a4.z;
        As[aoff + 3][arow] = a4.w;
        *(float4*)&Bs[brow    ][bcol] = *(const float4*)&B[(k0 + brow    ) * N + n0 + bcol];
        *(float4*)&Bs[brow + 1][bcol] = *(const float4*)&B[(k0 + brow + 1) * N + n0 + bcol];
        __syncthreads();
#pragma unroll
        for (int kk = 0; kk < 16; kk++) {
            float4 av = *(const float4*)&As[kk][ty * 4];
            const ulonglong2* bp = (const ulonglong2*)&Bs[kk][tx * 8];
            ulonglong2 b01 = bp[0];
            ulonglong2 b23 = bp[1];
            ull a0 = dup2(av.x), a1 = dup2(av.y), a2 = dup2(av.z), a3 = dup2(av.w);
            c2[0][0] = ffma2(a0, b01.x, c2[0][0]); c2[0][1] = ffma2(a0, b01.y, c2[0][1]);
            c2[0][2] = ffma2(a0, b23.x, c2[0][2]); c2[0][3] = ffma2(a0, b23.y, c2[0][3]);
            c2[1][0] = ffma2(a1, b01.x, c2[1][0]); c2[1][1] = ffma2(a1, b01.y, c2[1][1]);
            c2[1][2] = ffma2(a1, b23.x, c2[1][2]); c2[1][3] = ffma2(a1, b23.y, c2[1][3]);
            c2[2][0] = ffma2(a2, b01.x, c2[2][0]); c2[2][1] = ffma2(a2, b01.y, c2[2][1]);
            c2[2][2] = ffma2(a2, b23.x, c2[2][2]); c2[2][3] = ffma2(a2, b23.y, c2[2][3]);
            c2[3][0] = ffma2(a3, b01.x, c2[3][0]); c2[3][1] = ffma2(a3, b01.y, c2[3][1]);
            c2[3][2] = ffma2(a3, b23.x, c2[3][2]); c2[3][3] = ffma2(a3, b23.y, c2[3][3]);
        }
        __syncthreads();
    }
    int col = n0 + tx * 8;
    float4 bb0 = make_float4(0.f, 0.f, 0.f, 0.f);
    float4 bb1 = bb0;
    if (bias) {
        bb0 = *(const float4*)&bias[col];
        bb1 = *(const float4*)&bias[col + 4];
    }
#pragma unroll
    for (int i = 0; i < 4; i++) {
        float2 p0 = unpk(c2[i][0]);
        float2 p1 = unpk(c2[i][1]);
        float2 p2 = unpk(c2[i][2]);
        float2 p3 = unpk(c2[i][3]);
        float4 v0 = make_float4(p0.x + bb0.x, p0.y + bb0.y, p1.x + bb0.z, p1.y + bb0.w);
        float4 v1 = make_float4(p2.x + bb1.x, p2.y + bb1.y, p3.x + bb1.z, p3.y + bb1.w);
        float* crow = &C[(size_t)(m0 + ty * 4 + i) * N + col];
        *(float4*)crow = v0;
        *(float4*)(crow + 4) = v1;
    }
}

// ---------------- mb[i] = matrix[i,:] . fc_b ----------------
__global__ void k_mb(const float* __restrict__ matrix, const float* __restrict__ fc_b) {
    int warp = threadIdx.x >> 5, lane = threadIdx.x & 31;
    int i = blockIdx.x * 8 + warp;
    float s = 0.f;
    for (int q = lane; q < QN; q += 32) s = fmaf(matrix[i * QN + q], fc_b[q], s);
#pragma unroll
    for (int o = 16; o; o >>= 1) s += __shfl_down_sync(0xffffffffu, s, o);
    if (lane == 0) g_mb[i] = s;
}

// ---------------- persistent GRU scan ----------------
// 128 blocks x 256 threads, one block per SM (153KB dyn smem), all resident.
// Per step: cp.async-stage h_{t-1} (64x512) into padded smem, dot from smem,
// write h_t to g_hall, grid barrier via red.release + ld.acquire load-polling
// (monotonic counter, reset each launch by k_init).
#define HS_PITCH 516
#define SMEM_HS  (64 * HS_PITCH)
#define SMEM_WRZ (4 * 1032)
#define SMEM_WN  (4 * 520)
#define GRU_SMEM_BYTES ((SMEM_HS + SMEM_WRZ + SMEM_WN) * 4)

__global__ void __launch_bounds__(256) k_gru_all(const float* __restrict__ b_hh) {
    extern __shared__ float sm[];
    float* hs  = sm;                   // [64][516] padded h staging
    float* wrz = sm + SMEM_HS;         // [4][1032] interleaved (r,z) weights
    float* wn  = wrz + SMEM_WRZ;       // [4][520]  n-gate weights
    int tid = threadIdx.x;
    int j0 = blockIdx.x * 4;

    // stage weights once (broadcast-read layout, 8-bank offset per jj)
    for (int idx = tid; idx < 512 * 4; idx += 256) {
        int k = idx >> 2, jj = idx & 3;
        const float* base = g_whhT + k * G3 + j0 + jj;
        wrz[jj * 1032 + 2 * k]     = base[0];       // r
        wrz[jj * 1032 + 2 * k + 1] = base[HN];      // z
        wn [jj * 520 + k]          = base[2 * HN];  // n
    }

    int b = tid >> 2, jj = tid & 3;
    int j = j0 + jj;
    float bhr = b_hh[j], bhz = b_hh[HN + j], bhn = b_hh[2 * HN + j];
    const ulonglong2* w2  = (const ulonglong2*)(wrz + jj * 1032);
    const float4*     w4n = (const float4*)(wn + jj * 520);
    const float4*     hb4 = (const float4*)(hs + b * HS_PITCH);
    unsigned int hs_base = (unsigned int)__cvta_generic_to_shared(hs);
    unsigned int* pbar = &g_bar_count;
    unsigned int bar_target = 0;
    __syncthreads();

    for (int t = 0; t < LN; t++) {
        // ---- stage h_{t-1} into smem ----
        if (t == 0) {
            float4 z4 = make_float4(0.f, 0.f, 0.f, 0.f);
            for (int idx = tid; idx < 64 * 128; idx += 256) {
                int bb = idx >> 7, k4 = idx & 127;
                *(float4*)(hs + bb * HS_PITCH + k4 * 4) = z4;
            }
        } else {
#pragma unroll 8
            for (int idx = tid; idx < 64 * 128; idx += 256) {
                int bb = idx >> 7, k4 = idx & 127;
                const float* src = g_hall + ((size_t)(bb * LN + (t - 1))) * HN + k4 * 4;
                cpa16(hs_base + (unsigned int)(bb * HS_PITCH + k4 * 4) * 4u, src);
            }
            asm volatile("cp.async.commit_group;\n\tcp.async.wait_group 0;" ::: "memory");
        }
        __syncthreads();

        // ---- dot products from smem ----
        ull arz = 0ULL;       // packed (ar, az)
        float an = 0.f;
#pragma unroll 8
        for (int k4 = 0; k4 < 128; k4++) {
            float4 h4 = hb4[k4];
            ulonglong2 wA = w2[2 * k4];
            ulonglong2 wB = w2[2 * k4 + 1];
            float4 n4 = w4n[k4];
            arz = ffma2(wA.x, dup2(h4.x), arz);
            arz = ffma2(wA.y, dup2(h4.y), arz);
            arz = ffma2(wB.x, dup2(h4.z), arz);
            arz = ffma2(wB.y, dup2(h4.w), arz);
            an = fmaf(n4.x, h4.x, an); an = fmaf(n4.y, h4.y, an);
            an = fmaf(n4.z, h4.z, an); an = fmaf(n4.w, h4.w, an);
        }
        float2 rzv = unpk(arz);

        int bt = b * LN + t;
        const float* xgp = g_xg + (size_t)bt * G3;
        float hr = rzv.x + bhr;
        float hz = rzv.y + bhz;
        float hn = an + bhn;
        float r = 1.f / (1.f + expf(-(xgp[j] + hr)));
        float z = 1.f / (1.f + expf(-(xgp[HN + j] + hz)));
        float n = tanhf(xgp[2 * HN + j] + r * hn);
        float hold = hs[b * HS_PITCH + j];
        float hnew = (1.f - z) * n + z * hold;
        g_hall[(size_t)bt * HN + j] = hnew;

        // ---- grid barrier (monotonic; release-arrive + acquire-load poll) ----
        bar_target += NBLK;
        __syncthreads();                // all block writes issued, hs reads done
        if (tid == 0) {
            __threadfence();
            asm volatile("red.release.gpu.global.add.u32 [%0], 1;" :: "l"(pbar) : "memory");
            unsigned int v;
            do {
                asm volatile("ld.acquire.gpu.global.u32 %0, [%1];" : "=r"(v) : "l"(pbar) : "memory");
            } while (v < bar_target);
        }
        __syncthreads();
    }
}

// ---------------- mval[b,t] = threshold( h[b,t,:] . M2[idx,:] + mb[idx] ) ----------------
__global__ void k_mval() {
    int warp = threadIdx.x >> 5, lane = threadIdx.x & 31;
    int bt = blockIdx.x * 8 + warp;
    int i = g_idx[bt];
    const float* hp = g_hall + (size_t)bt * HN;
    const float* m2 = g_M2 + i * HN;
    float s = 0.f;
#pragma unroll 4
    for (int k = lane; k < HN; k += 32) s = fmaf(hp[k], m2[k], s);
#pragma unroll
    for (int o = 16; o; o >>= 1) s += __shfl_down_sync(0xffffffffu, s, o);
    if (lane == 0) {
        float v = s + g_mb[i];
        g_mval[bt] = (v >= 0.4f) ? 1.0f : v;
    }
}

// ---------------- counters + closed-form DINA -> preds ----------------
// guess/slip recurrence resolved per same-question chain:
//   guess slot before t = g_upd at latest occurrence k<t with !us_k (else 0)
//   slip  slot before t = mi_k/aa_k at latest occurrence k<t with us_k (else 0)
__global__ void k_counts(const int* __restrict__ qd) {
    __shared__ int   qs[LN];
    __shared__ float ms[LN];
    __shared__ int   qas[LN];
    __shared__ float a1m[LN], a0m[LN], a0n[LN];
    int b = blockIdx.x;
    int tid = threadIdx.x;
    if (tid < LN) {
        int bt = b * LN + tid;
        int q = qd[bt];
        float m = g_mval[bt];
        int qa = g_qa[bt];
        float mast = (m == 1.0f) ? 1.f : 0.f;
        float notm = (m == 0.0f) ? 1.f : 0.f;
        qs[tid] = q; ms[tid] = m; qas[tid] = qa;
        a1m[tid] = (qa == 1) ? mast : 0.f;
        a0m[tid] = (qa == 0) ? mast : 0.f;
        a0n[tid] = (qa == 0) ? notm : 0.f;
    }
    __syncthreads();
    if (tid < LN) {
        int qt = qs[tid];
        float mc = 0.f, mi = 0.f, nmc = 0.f;
        int cnt = 0;
        float last_gu = 0.f;   // g_upd at latest non-us occurrence
        float last_ss = 0.f;   // mi/aa at latest us occurrence
        for (int k = 0; k < tid; k++) {
            if (qs[k] == qt) {
                float aak = (float)(cnt + 1);
                float mk = ms[k];
                int qak = qas[k];
                bool usk = (mk == 1.0f) && (qak == 0);
                if (usk) {
                    last_ss = mi / aak;
                } else {
                    float gu;
                    if (mk == 1.0f)     gu = mc / aak;
                    else if (qak == 0)  gu = 1.0f - nmc / aak;
                    else                gu = nmc / aak;
                    last_gu = gu;
                }
                mc += a1m[k]; mi += a0m[k]; nmc += a0n[k]; cnt++;
            }
        }
        float aat = (float)(cnt + 1);
        float mt = ms[tid];
        int qat = qas[tid];
        bool ust = (mt == 1.0f) && (qat == 0);
        float ng, ns;
        if (ust) {
            ng = last_gu;
            ns = mi / aat;
        } else {
            if (mt == 1.0f)     ng = mc / aat;
            else if (qat == 0)  ng = 1.0f - nmc / aat;
            else                ng = nmc / aat;
            ns = last_ss;
        }
        float p = (1.f - ns) * (mt * ng + (1.f - ns) * (1.f - mt));
        g_preds[b * LN + tid] = p;
    }
}

// ---------------- final: sigmoid, masked MSE + c_reg, mask count ----------------
__global__ void k_final(const float* __restrict__ target, const int* __restrict__ pidd,
                        const float* __restrict__ diff_parm, float* __restrict__ out,
                        int out_size) {
    __shared__ double sm_[256];
    __shared__ double sc_[256];
    __shared__ int    si_[256];
    int tid = threadIdx.x;
    int poff = (out_size >= BL + 2) ? 1 : 0;
    double mse = 0.0, cr = 0.0;
    int cnt = 0;
    for (int i = tid; i < BL; i += 256) {
        float p = g_preds[i];
        if (poff + i < out_size) out[poff + i] = 1.f / (1.f + expf(-p));
        float lab = target[i];
        if (lab > -0.9f) { double d = (double)p - (double)lab; mse += d * d; cnt++; }
        float pe = diff_parm[pidd[i]];
        cr += (double)pe * (double)pe;
    }
    sm_[tid] = mse; sc_[tid] = cr; si_[tid] = cnt;
    __syncthreads();
    for (int o = 128; o; o >>= 1) {
        if (tid < o) { sm_[tid] += sm_[tid + o]; sc_[tid] += sc_[tid + o]; si_[tid] += si_[tid + o]; }
        __syncthreads();
    }
    if (tid == 0) {
        float loss = (float)(sm_[0] + sc_[0] * 1e-5);
        if (out_size >= BL + 2) {
            out[0] = loss;
            out[BL + 1] = (float)si_[0];
        } else if (out_size == 1) {
            out[0] = loss;
        }
    }
}

// ---------------- launch ----------------
extern "C" void kernel_launch(void* const* d_in, const int* in_sizes, int n_in,
                              void* d_out, int out_size) {
    const int*   qd          = (const int*)  d_in[0];
    const int*   qad         = (const int*)  d_in[1];
    const int*   pidd        = (const int*)  d_in[2];
    const float* matrix      = (const float*)d_in[3];
    const float* target      = (const float*)d_in[4];
    const float* q_emb       = (const float*)d_in[5];
    const float* qa_emb      = (const float*)d_in[6];
    const float* q_emb_diff  = (const float*)d_in[7];
    const float* qa_emb_diff = (const float*)d_in[8];
    const float* diff_parm   = (const float*)d_in[9];
    const float* w_ih        = (const float*)d_in[10];
    const float* w_hh        = (const float*)d_in[11];
    const float* b_ih        = (const float*)d_in[12];
    const float* b_hh        = (const float*)d_in[13];
    const float* fc_w        = (const float*)d_in[14];
    const float* fc_b        = (const float*)d_in[15];
    float* out = (float*)d_out;

    // Device symbol addresses MUST come from cudaGetSymbolAddress — using the
    // symbol name in host code yields the host shadow (ATS silently reads it!).
    float *px, *pxg, *pwihT, *pM2;
    cudaGetSymbolAddress((void**)&px,    g_x);
    cudaGetSymbolAddress((void**)&pxg,   g_xg);
    cudaGetSymbolAddress((void**)&pwihT, g_wihT);
    cudaGetSymbolAddress((void**)&pM2,   g_M2);

    static int smem_set = 0;
    if (!smem_set) {
        cudaFuncSetAttribute(k_gru_all, cudaFuncAttributeMaxDynamicSharedMemorySize,
                             GRU_SMEM_BYTES);
        smem_set = 1;
    }

    k_init<<<1, 32>>>();
    k_transpose<<<256, 256>>>(w_ih, w_hh);
    k_embed<<<BL, 256>>>(qd, qad, pidd, q_emb, qa_emb, q_emb_diff, qa_emb_diff, diff_parm);

    // xg = x @ w_ih^T + b_ih : M=12800, N=1536, K=512
    k_sgemm<<<dim3(G3 / 128, BL / 64), 256>>>(px, pwihT, b_ih, pxg, BL, G3, TWO_D);
    // M2 = matrix @ fc_w : M=1024, N=512, K=1024
    k_sgemm<<<dim3(HN / 128, QN / 64), 256>>>(matrix, fc_w, nullptr, pM2, QN, HN, QN);
    k_mb<<<128, 256>>>(matrix, fc_b);

    // persistent GRU scan: one launch for all 200 steps
    k_gru_all<<<NBLK, 256, GRU_SMEM_BYTES>>>(b_hh);

    k_mval<<<BL / 8, 256>>>();
    k_counts<<<BN, 256>>>(qd);
    k_final<<<1, 256>>>(target, pidd, diff_parm, out, out_size);
}

// round 15
// speedup vs baseline: 1.7547x; 1.3054x over previous
#include <cuda_runtime.h>
#include <math.h>

// ---------------- problem constants ----------------
#define BN   64
#define LN   200
#define BL   12800          // BN*LN
#define DN   256
#define TWO_D 512
#define HN   512
#define G3   1536           // 3*HN
#define QN   1024
#define NQ   1024
#define NBLK 128            // persistent GRU blocks (1/SM, <=148 SMs, all resident)

typedef unsigned long long ull;

// ---------------- f32x2 packed-math helpers (sm_100+) ----------------
__device__ __forceinline__ ull dup2(float x) {
    ull r; asm("mov.b64 %0, {%1, %1};" : "=l"(r) : "f"(x)); return r;
}
__device__ __forceinline__ ull ffma2(ull a, ull b, ull c) {
    ull d; asm("fma.rn.f32x2 %0, %1, %2, %3;" : "=l"(d) : "l"(a), "l"(b), "l"(c)); return d;
}
__device__ __forceinline__ float2 unpk(ull v) {
    float2 f; asm("mov.b64 {%0, %1}, %2;" : "=f"(f.x), "=f"(f.y) : "l"(v)); return f;
}
__device__ __forceinline__ void cpa16(unsigned int s, const void* g) {
    asm volatile("cp.async.cg.shared.global [%0], [%1], 16;" :: "r"(s), "l"(g) : "memory");
}

// ---------------- device scratch (static, no allocation) ----------------
__device__ float g_x   [BL * TWO_D];   // [12800,512]  GRU input
__device__ float g_xg  [BL * G3];      // [12800,1536] x@w_ih^T + b_ih
__device__ float g_wihT[TWO_D * G3];   // [512,1536]
__device__ float g_whhT[HN * G3];      // [512,1536]
__device__ float g_hall[BL * HN];      // all hidden states [b,t,h]
__device__ float g_M2  [QN * HN];      // matrix @ fc_w
__device__ float g_mb  [QN];           // matrix @ fc_b
__device__ float g_mval[BL];
__device__ int   g_idx [BL];           // q-1
__device__ int   g_qa  [BL];           // answer 0/1
__device__ float g_preds[BL];
__device__ unsigned int g_bar_count;   // monotonic grid-barrier arrival counter

// ---------------- init: reset barrier counter ----------------
__global__ void k_init() {
    if (threadIdx.x == 0 && blockIdx.x == 0) g_bar_count = 0u;
}

// ---------------- transpose w_ih, w_hh ([1536,512] -> [512,1536]) ----------------
__global__ void k_transpose(const float* __restrict__ w_ih,
                            const float* __restrict__ w_hh) {
    int idx = blockIdx.x * blockDim.x + threadIdx.x;
    int stride = gridDim.x * blockDim.x;
    const int total = G3 * TWO_D;
    for (int i = idx; i < total; i += stride) {
        int r = i / TWO_D;       // gate row 0..1535
        int k = i - r * TWO_D;   // 0..511
        g_wihT[k * G3 + r] = w_ih[i];
        g_whhT[k * G3 + r] = w_hh[i];
    }
}

// ---------------- embeddings -> x ----------------
__global__ void k_embed(const int* __restrict__ qd, const int* __restrict__ qad,
                        const int* __restrict__ pidd,
                        const float* __restrict__ q_emb, const float* __restrict__ qa_emb,
                        const float* __restrict__ q_emb_diff,
                        const float* __restrict__ qa_emb_diff,
                        const float* __restrict__ diff_parm) {
    int bt = blockIdx.x;
    int d  = threadIdx.x;            // 0..255
    int q  = qd[bt];
    int qa = (qad[bt] - q) / NQ;     // 0 or 1
    float pid = diff_parm[pidd[bt]];
    float qe  = q_emb[q * DN + d];
    float qav = qa_emb[qa * DN + d] + qe + pid * qa_emb_diff[qa * DN + d];
    float qv  = qe + pid * q_emb_diff[q * DN + d];
    g_x[bt * TWO_D + d]      = qav;  // qa_embed2
    g_x[bt * TWO_D + DN + d] = qv;   // q_embed2
    if (d == 0) { g_idx[bt] = q - 1; g_qa[bt] = qa; }
}

// ---------------- fp32 SGEMM, f32x2 packed, 64Mx128N tile, 4x8 microtile ----------------
// Thread's 8 N-columns are split {tx*4..+3} and {64+tx*4..+3}: both groups are
// 16B-stride across the 16 tx lanes -> conflict-free LDS.128. Next K-tile is
// prefetched into registers while the current tile computes.
__global__ void __launch_bounds__(256) k_sgemm(
        const float* __restrict__ A, const float* __restrict__ B,
        const float* __restrict__ bias, float* __restrict__ C,
        int M, int N, int K) {
    __shared__ __align__(16) float As[16][64];
    __shared__ __align__(16) float Bs[16][128];
    int tid = threadIdx.x;
    int n0 = blockIdx.x * 128;
    int m0 = blockIdx.y * 64;
    int tx = tid & 15;        // N dir
    int ty = tid >> 4;        // M dir, 4 rows each
    int arow = tid >> 2;            // 0..63
    int aoff = (tid & 3) * 4;       // 0,4,8,12
    int brow = (tid >> 5) * 2;      // 0,2,..,14
    int bcol = (tid & 31) * 4;      // 0..124

    // prefetch k0 = 0
    float4 a_nxt  = *(const float4*)&A[(size_t)(m0 + arow) * K + aoff];
    float4 b_nxt0 = *(const float4*)&B[(size_t)(brow    ) * N + n0 + bcol];
    float4 b_nxt1 = *(const float4*)&B[(size_t)(brow + 1) * N + n0 + bcol];

    ull c2[4][4] = {};
    for (int k0 = 0; k0 < K; k0 += 16) {
        As[aoff + 0][arow] = a_nxt.x;
        As[aoff + 1][arow] = a_nxt.y;
        As[aoff + 2][arow] = a_nxt.z;
        As[aoff + 3][arow] = a_nxt.w;
        *(float4*)&Bs[brow    ][bcol] = b_nxt0;
        *(float4*)&Bs[brow + 1][bcol] = b_nxt1;
        __syncthreads();
        if (k0 + 16 < K) {
            a_nxt  = *(const float4*)&A[(size_t)(m0 + arow) * K + k0 + 16 + aoff];
            b_nxt0 = *(const float4*)&B[(size_t)(k0 + 16 + brow    ) * N + n0 + bcol];
            b_nxt1 = *(const float4*)&B[(size_t)(k0 + 16 + brow + 1) * N + n0 + bcol];
        }
#pragma unroll
        for (int kk = 0; kk < 16; kk++) {
            float4 av = *(const float4*)&As[kk][ty * 4];
            ulonglong2 b01 = *(const ulonglong2*)&Bs[kk][tx * 4];        // cols tx*4..+3
            ulonglong2 b23 = *(const ulonglong2*)&Bs[kk][64 + tx * 4];   // cols 64+tx*4..+3
            ull a0 = dup2(av.x), a1 = dup2(av.y), a2 = dup2(av.z), a3 = dup2(av.w);
            c2[0][0] = ffma2(a0, b01.x, c2[0][0]); c2[0][1] = ffma2(a0, b01.y, c2[0][1]);
            c2[0][2] = ffma2(a0, b23.x, c2[0][2]); c2[0][3] = ffma2(a0, b23.y, c2[0][3]);
            c2[1][0] = ffma2(a1, b01.x, c2[1][0]); c2[1][1] = ffma2(a1, b01.y, c2[1][1]);
            c2[1][2] = ffma2(a1, b23.x, c2[1][2]); c2[1][3] = ffma2(a1, b23.y, c2[1][3]);
            c2[2][0] = ffma2(a2, b01.x, c2[2][0]); c2[2][1] = ffma2(a2, b01.y, c2[2][1]);
            c2[2][2] = ffma2(a2, b23.x, c2[2][2]); c2[2][3] = ffma2(a2, b23.y, c2[2][3]);
            c2[3][0] = ffma2(a3, b01.x, c2[3][0]); c2[3][1] = ffma2(a3, b01.y, c2[3][1]);
            c2[3][2] = ffma2(a3, b23.x, c2[3][2]); c2[3][3] = ffma2(a3, b23.y, c2[3][3]);
        }
        __syncthreads();
    }
    int col0 = n0 + tx * 4;
    int col1 = n0 + 64 + tx * 4;
    float4 bb0 = make_float4(0.f, 0.f, 0.f, 0.f);
    float4 bb1 = bb0;
    if (bias) {
        bb0 = *(const float4*)&bias[col0];
        bb1 = *(const float4*)&bias[col1];
    }
#pragma unroll
    for (int i = 0; i < 4; i++) {
        float2 p0 = unpk(c2[i][0]);
        float2 p1 = unpk(c2[i][1]);
        float2 p2 = unpk(c2[i][2]);
        float2 p3 = unpk(c2[i][3]);
        float4 v0 = make_float4(p0.x + bb0.x, p0.y + bb0.y, p1.x + bb0.z, p1.y + bb0.w);
        float4 v1 = make_float4(p2.x + bb1.x, p2.y + bb1.y, p3.x + bb1.z, p3.y + bb1.w);
        float* crow = &C[(size_t)(m0 + ty * 4 + i) * N];
        *(float4*)(crow + col0) = v0;
        *(float4*)(crow + col1) = v1;
    }
}

// ---------------- mb[i] = matrix[i,:] . fc_b ----------------
__global__ void k_mb(const float* __restrict__ matrix, const float* __restrict__ fc_b) {
    int warp = threadIdx.x >> 5, lane = threadIdx.x & 31;
    int i = blockIdx.x * 8 + warp;
    float s = 0.f;
    for (int q = lane; q < QN; q += 32) s = fmaf(matrix[i * QN + q], fc_b[q], s);
#pragma unroll
    for (int o = 16; o; o >>= 1) s += __shfl_down_sync(0xffffffffu, s, o);
    if (lane == 0) g_mb[i] = s;
}

// ---------------- persistent GRU scan ----------------
// 128 blocks x 256 threads, one block per SM, all resident. Thread = (b,jj).
// Gate dots accumulate with f32x2 over k-pairs (weights/h contiguous in k).
// h_{t-1} staged smem via 4 chunked cp.async groups overlapped with the dot
// (wait_group 3/2/1/0). Grid barrier: red.release + ld.acquire load polling.
#define HS_PITCH 516
#define W_PITCH  516
#define SMEM_HS  (64 * HS_PITCH)
#define GRU_SMEM_BYTES ((SMEM_HS + 12 * W_PITCH) * 4)

__global__ void __launch_bounds__(256) k_gru_all(const float* __restrict__ b_hh) {
    extern __shared__ float smbuf[];
    float* hs = smbuf;                   // [64][516] h staging
    float* wr = smbuf + SMEM_HS;         // [4][516]
    float* wz = wr + 4 * W_PITCH;        // [4][516]
    float* wn = wz + 4 * W_PITCH;        // [4][516]
    int tid = threadIdx.x;
    int j0 = blockIdx.x * 4;

    // stage weights once: wX[jj][k] = w_hh[gate*512 + j0+jj][k]
    for (int idx = tid; idx < 2048; idx += 256) {
        int k = idx >> 2, jj = idx & 3;
        const float* base = g_whhT + k * G3 + j0 + jj;
        wr[jj * W_PITCH + k] = base[0];
        wz[jj * W_PITCH + k] = base[HN];
        wn[jj * W_PITCH + k] = base[2 * HN];
    }

    int b = tid >> 2, jj = tid & 3;
    int j = j0 + jj;
    float bhr = b_hh[j], bhz = b_hh[HN + j], bhn = b_hh[2 * HN + j];
    const ulonglong2* hb  = (const ulonglong2*)(hs + b * HS_PITCH);
    const ulonglong2* wrp = (const ulonglong2*)(wr + jj * W_PITCH);
    const ulonglong2* wzp = (const ulonglong2*)(wz + jj * W_PITCH);
    const ulonglong2* wnp = (const ulonglong2*)(wn + jj * W_PITCH);
    unsigned int hs_base = (unsigned int)__cvta_generic_to_shared(hs);
    unsigned int* pbar = &g_bar_count;
    unsigned int bar_target = 0;

    // t=0: zero-fill h staging
    float4 zf = make_float4(0.f, 0.f, 0.f, 0.f);
    for (int idx = tid; idx < 8192; idx += 256) {
        int bb = idx >> 7, kq = idx & 127;
        *(float4*)(hs + bb * HS_PITCH + kq * 4) = zf;
    }
    __syncthreads();

    for (int t = 0; t < LN; t++) {
        // ---- issue staged h_{t-1} loads in 4 chunks (t>0) ----
        if (t > 0) {
#pragma unroll
            for (int c = 0; c < 4; c++) {
#pragma unroll
                for (int i = 0; i < 8; i++) {
                    int idx = i * 256 + tid;           // 0..2047
                    int bb = idx >> 5;                 // 0..63
                    int k4 = c * 32 + (idx & 31);      // chunk's k4 range
                    const float* src = g_hall + ((size_t)(bb * LN + (t - 1))) * HN + k4 * 4;
                    cpa16(hs_base + (unsigned int)(bb * HS_PITCH + k4 * 4) * 4u, src);
                }
                asm volatile("cp.async.commit_group;" ::: "memory");
            }
        }

        // xg operands prefetch (independent of h)
        int bt = b * LN + t;
        const float* xgp = g_xg + (size_t)bt * G3;
        float xr = xgp[j], xz = xgp[HN + j], xn = xgp[2 * HN + j];

        // ---- chunked dot, overlapped with remaining staging ----
        ull r2 = 0ULL, z2 = 0ULL, n2 = 0ULL;   // f32x2 accumulators over k-pairs
#pragma unroll
        for (int c = 0; c < 4; c++) {
            if (t > 0) {
                if      (c == 0) asm volatile("cp.async.wait_group 3;" ::: "memory");
                else if (c == 1) asm volatile("cp.async.wait_group 2;" ::: "memory");
                else if (c == 2) asm volatile("cp.async.wait_group 1;" ::: "memory");
                else             asm volatile("cp.async.wait_group 0;" ::: "memory");
            }
            __syncthreads();
#pragma unroll 8
            for (int k4 = c * 32; k4 < c * 32 + 32; k4++) {
                ulonglong2 h2 = hb[k4];
                ulonglong2 w_r = wrp[k4];
                ulonglong2 w_z = wzp[k4];
                ulonglong2 w_n = wnp[k4];
                r2 = ffma2(w_r.x, h2.x, r2); r2 = ffma2(w_r.y, h2.y, r2);
                z2 = ffma2(w_z.x, h2.x, z2); z2 = ffma2(w_z.y, h2.y, z2);
                n2 = ffma2(w_n.x, h2.x, n2); n2 = ffma2(w_n.y, h2.y, n2);
            }
        }
        float2 rv = unpk(r2), zv = unpk(z2), nv = unpk(n2);
        float hr = (rv.x + rv.y) + bhr;
        float hz = (zv.x + zv.y) + bhz;
        float hn = (nv.x + nv.y) + bhn;
        float r = 1.f / (1.f + expf(-(xr + hr)));
        float z = 1.f / (1.f + expf(-(xz + hz)));
        float n = tanhf(xn + r * hn);
        float hold = hs[b * HS_PITCH + j];
        float hnew = (1.f - z) * n + z * hold;
        g_hall[(size_t)bt * HN + j] = hnew;

        // ---- grid barrier (skip after last step) ----
        if (t + 1 < LN) {
            bar_target += NBLK;
            __syncthreads();             // all block writes issued, hs reads done
            if (tid == 0) {
                __threadfence();
                asm volatile("red.release.gpu.global.add.u32 [%0], 1;" :: "l"(pbar) : "memory");
                unsigned int v;
                do {
                    asm volatile("ld.acquire.gpu.global.u32 %0, [%1];" : "=r"(v) : "l"(pbar) : "memory");
                } while (v < bar_target);
            }
            __syncthreads();
        }
    }
}

// ---------------- mval[b,t] = threshold( h[b,t,:] . M2[idx,:] + mb[idx] ) ----------------
__global__ void k_mval() {
    int warp = threadIdx.x >> 5, lane = threadIdx.x & 31;
    int bt = blockIdx.x * 8 + warp;
    int i = g_idx[bt];
    const float* hp = g_hall + (size_t)bt * HN;
    const float* m2 = g_M2 + i * HN;
    float s = 0.f;
#pragma unroll 4
    for (int k = lane; k < HN; k += 32) s = fmaf(hp[k], m2[k], s);
#pragma unroll
    for (int o = 16; o; o >>= 1) s += __shfl_down_sync(0xffffffffu, s, o);
    if (lane == 0) {
        float v = s + g_mb[i];
        g_mval[bt] = (v >= 0.4f) ? 1.0f : v;
    }
}

// ---------------- counters + closed-form DINA -> preds ----------------
__global__ void k_counts(const int* __restrict__ qd) {
    __shared__ int   qs[LN];
    __shared__ float ms[LN];
    __shared__ int   qas[LN];
    __shared__ float a1m[LN], a0m[LN], a0n[LN];
    int b = blockIdx.x;
    int tid = threadIdx.x;
    if (tid < LN) {
        int bt = b * LN + tid;
        int q = qd[bt];
        float m = g_mval[bt];
        int qa = g_qa[bt];
        float mast = (m == 1.0f) ? 1.f : 0.f;
        float notm = (m == 0.0f) ? 1.f : 0.f;
        qs[tid] = q; ms[tid] = m; qas[tid] = qa;
        a1m[tid] = (qa == 1) ? mast : 0.f;
        a0m[tid] = (qa == 0) ? mast : 0.f;
        a0n[tid] = (qa == 0) ? notm : 0.f;
    }
    __syncthreads();
    if (tid < LN) {
        int qt = qs[tid];
        float mc = 0.f, mi = 0.f, nmc = 0.f;
        int cnt = 0;
        float last_gu = 0.f;   // g_upd at latest non-us occurrence
        float last_ss = 0.f;   // mi/aa at latest us occurrence
        for (int k = 0; k < tid; k++) {
            if (qs[k] == qt) {
                float aak = (float)(cnt + 1);
                float mk = ms[k];
                int qak = qas[k];
                bool usk = (mk == 1.0f) && (qak == 0);
                if (usk) {
                    last_ss = mi / aak;
                } else {
                    float gu;
                    if (mk == 1.0f)     gu = mc / aak;
                    else if (qak == 0)  gu = 1.0f - nmc / aak;
                    else                gu = nmc / aak;
                    last_gu = gu;
                }
                mc += a1m[k]; mi += a0m[k]; nmc += a0n[k]; cnt++;
            }
        }
        float aat = (float)(cnt + 1);
        float mt = ms[tid];
        int qat = qas[tid];
        bool ust = (mt == 1.0f) && (qat == 0);
        float ng, ns;
        if (ust) {
            ng = last_gu;
            ns = mi / aat;
        } else {
            if (mt == 1.0f)     ng = mc / aat;
            else if (qat == 0)  ng = 1.0f - nmc / aat;
            else                ng = nmc / aat;
            ns = last_ss;
        }
        float p = (1.f - ns) * (mt * ng + (1.f - ns) * (1.f - mt));
        g_preds[b * LN + tid] = p;
    }
}

// ---------------- final: sigmoid, masked MSE + c_reg, mask count ----------------
__global__ void k_final(const float* __restrict__ target, const int* __restrict__ pidd,
                        const float* __restrict__ diff_parm, float* __restrict__ out,
                        int out_size) {
    __shared__ double sm_[256];
    __shared__ double sc_[256];
    __shared__ int    si_[256];
    int tid = threadIdx.x;
    int poff = (out_size >= BL + 2) ? 1 : 0;
    double mse = 0.0, cr = 0.0;
    int cnt = 0;
    for (int i = tid; i < BL; i += 256) {
        float p = g_preds[i];
        if (poff + i < out_size) out[poff + i] = 1.f / (1.f + expf(-p));
        float lab = target[i];
        if (lab > -0.9f) { double d = (double)p - (double)lab; mse += d * d; cnt++; }
        float pe = diff_parm[pidd[i]];
        cr += (double)pe * (double)pe;
    }
    sm_[tid] = mse; sc_[tid] = cr; si_[tid] = cnt;
    __syncthreads();
    for (int o = 128; o; o >>= 1) {
        if (tid < o) { sm_[tid] += sm_[tid + o]; sc_[tid] += sc_[tid + o]; si_[tid] += si_[tid + o]; }
        __syncthreads();
    }
    if (tid == 0) {
        float loss = (float)(sm_[0] + sc_[0] * 1e-5);
        if (out_size >= BL + 2) {
            out[0] = loss;
            out[BL + 1] = (float)si_[0];
        } else if (out_size == 1) {
            out[0] = loss;
        }
    }
}

// ---------------- launch ----------------
extern "C" void kernel_launch(void* const* d_in, const int* in_sizes, int n_in,
                              void* d_out, int out_size) {
    const int*   qd          = (const int*)  d_in[0];
    const int*   qad         = (const int*)  d_in[1];
    const int*   pidd        = (const int*)  d_in[2];
    const float* matrix      = (const float*)d_in[3];
    const float* target      = (const float*)d_in[4];
    const float* q_emb       = (const float*)d_in[5];
    const float* qa_emb      = (const float*)d_in[6];
    const float* q_emb_diff  = (const float*)d_in[7];
    const float* qa_emb_diff = (const float*)d_in[8];
    const float* diff_parm   = (const float*)d_in[9];
    const float* w_ih        = (const float*)d_in[10];
    const float* w_hh        = (const float*)d_in[11];
    const float* b_ih        = (const float*)d_in[12];
    const float* b_hh        = (const float*)d_in[13];
    const float* fc_w        = (const float*)d_in[14];
    const float* fc_b        = (const float*)d_in[15];
    float* out = (float*)d_out;

    // Device symbol addresses MUST come from cudaGetSymbolAddress — using the
    // symbol name in host code yields the host shadow (ATS silently reads it!).
    float *px, *pxg, *pwihT, *pM2;
    cudaGetSymbolAddress((void**)&px,    g_x);
    cudaGetSymbolAddress((void**)&pxg,   g_xg);
    cudaGetSymbolAddress((void**)&pwihT, g_wihT);
    cudaGetSymbolAddress((void**)&pM2,   g_M2);

    static int smem_set = 0;
    if (!smem_set) {
        cudaFuncSetAttribute(k_gru_all, cudaFuncAttributeMaxDynamicSharedMemorySize,
                             GRU_SMEM_BYTES);
        smem_set = 1;
    }

    k_init<<<1, 32>>>();
    k_transpose<<<256, 256>>>(w_ih, w_hh);
    k_embed<<<BL, 256>>>(qd, qad, pidd, q_emb, qa_emb, q_emb_diff, qa_emb_diff, diff_parm);

    // xg = x @ w_ih^T + b_ih : M=12800, N=1536, K=512
    k_sgemm<<<dim3(G3 / 128, BL / 64), 256>>>(px, pwihT, b_ih, pxg, BL, G3, TWO_D);
    // M2 = matrix @ fc_w : M=1024, N=512, K=1024
    k_sgemm<<<dim3(HN / 128, QN / 64), 256>>>(matrix, fc_w, nullptr, pM2, QN, HN, QN);
    k_mb<<<128, 256>>>(matrix, fc_b);

    // persistent GRU scan: one launch for all 200 steps
    k_gru_all<<<NBLK, 256, GRU_SMEM_BYTES>>>(b_hh);

    k_mval<<<BL / 8, 256>>>();
    k_counts<<<BN, 256>>>(qd);
    k_final<<<1, 256>>>(target, pidd, diff_parm, out, out_size);
}

// round 16
// speedup vs baseline: 1.9725x; 1.1241x over previous
#include <cuda_runtime.h>
#include <math.h>

// ---------------- problem constants ----------------
#define BN   64
#define LN   200
#define BL   12800          // BN*LN
#define DN   256
#define TWO_D 512
#define HN   512
#define G3   1536           // 3*HN
#define QN   1024
#define NQ   1024
#define NBLK 128            // persistent GRU blocks (1/SM, <=148 SMs, all resident)

typedef unsigned long long ull;

// ---------------- f32x2 packed-math helpers (sm_100+) ----------------
__device__ __forceinline__ ull dup2(float x) {
    ull r; asm("mov.b64 %0, {%1, %1};" : "=l"(r) : "f"(x)); return r;
}
__device__ __forceinline__ ull ffma2(ull a, ull b, ull c) {
    ull d; asm("fma.rn.f32x2 %0, %1, %2, %3;" : "=l"(d) : "l"(a), "l"(b), "l"(c)); return d;
}
__device__ __forceinline__ float2 unpk(ull v) {
    float2 f; asm("mov.b64 {%0, %1}, %2;" : "=f"(f.x), "=f"(f.y) : "l"(v)); return f;
}
__device__ __forceinline__ void cpa16(unsigned int s, const void* g) {
    asm volatile("cp.async.cg.shared.global [%0], [%1], 16;" :: "r"(s), "l"(g) : "memory");
}

// ---------------- device scratch (static, no allocation) ----------------
__device__ float g_x   [BL * TWO_D];   // [12800,512]  GRU input
__device__ float g_xg  [BL * G3];      // [12800,1536] x@w_ih^T + b_ih
__device__ float g_wihT[TWO_D * G3];   // [512,1536]
__device__ float g_hall[BL * HN];      // all hidden states [b,t,h]
__device__ float g_M2  [QN * HN];      // matrix @ fc_w
__device__ float g_mb  [QN];           // matrix @ fc_b
__device__ float g_mval[BL];
__device__ int   g_idx [BL];           // q-1
__device__ int   g_qa  [BL];           // answer 0/1
__device__ float g_preds[BL];
__device__ unsigned int g_bar_count;   // monotonic grid-barrier arrival counter

// ---------------- init: reset barrier counter ----------------
__global__ void k_init() {
    if (threadIdx.x == 0 && blockIdx.x == 0) g_bar_count = 0u;
}

// ---------------- transpose w_ih ([1536,512] -> [512,1536]) ----------------
__global__ void k_transpose(const float* __restrict__ w_ih) {
    int idx = blockIdx.x * blockDim.x + threadIdx.x;
    int stride = gridDim.x * blockDim.x;
    const int total = G3 * TWO_D;
    for (int i = idx; i < total; i += stride) {
        int r = i / TWO_D;       // gate row 0..1535
        int k = i - r * TWO_D;   // 0..511
        g_wihT[k * G3 + r] = w_ih[i];
    }
}

// ---------------- embeddings -> x ----------------
__global__ void k_embed(const int* __restrict__ qd, const int* __restrict__ qad,
                        const int* __restrict__ pidd,
                        const float* __restrict__ q_emb, const float* __restrict__ qa_emb,
                        const float* __restrict__ q_emb_diff,
                        const float* __restrict__ qa_emb_diff,
                        const float* __restrict__ diff_parm) {
    int bt = blockIdx.x;
    int d  = threadIdx.x;            // 0..255
    int q  = qd[bt];
    int qa = (qad[bt] - q) / NQ;     // 0 or 1
    float pid = diff_parm[pidd[bt]];
    float qe  = q_emb[q * DN + d];
    float qav = qa_emb[qa * DN + d] + qe + pid * qa_emb_diff[qa * DN + d];
    float qv  = qe + pid * q_emb_diff[q * DN + d];
    g_x[bt * TWO_D + d]      = qav;  // qa_embed2
    g_x[bt * TWO_D + DN + d] = qv;   // q_embed2
    if (d == 0) { g_idx[bt] = q - 1; g_qa[bt] = qa; }
}

// ---------------- fp32 SGEMM, f32x2 packed, 64Mx128N tile, 4x8 microtile ----------------
__global__ void __launch_bounds__(256) k_sgemm(
        const float* __restrict__ A, const float* __restrict__ B,
        const float* __restrict__ bias, float* __restrict__ C,
        int M, int N, int K) {
    __shared__ __align__(16) float As[16][64];
    __shared__ __align__(16) float Bs[16][128];
    int tid = threadIdx.x;
    int n0 = blockIdx.x * 128;
    int m0 = blockIdx.y * 64;
    int tx = tid & 15;        // N dir
    int ty = tid >> 4;        // M dir, 4 rows each
    int arow = tid >> 2;            // 0..63
    int aoff = (tid & 3) * 4;       // 0,4,8,12
    int brow = (tid >> 5) * 2;      // 0,2,..,14
    int bcol = (tid & 31) * 4;      // 0..124

    // prefetch k0 = 0
    float4 a_nxt  = *(const float4*)&A[(size_t)(m0 + arow) * K + aoff];
    float4 b_nxt0 = *(const float4*)&B[(size_t)(brow    ) * N + n0 + bcol];
    float4 b_nxt1 = *(const float4*)&B[(size_t)(brow + 1) * N + n0 + bcol];

    ull c2[4][4] = {};
    for (int k0 = 0; k0 < K; k0 += 16) {
        As[aoff + 0][arow] = a_nxt.x;
        As[aoff + 1][arow] = a_nxt.y;
        As[aoff + 2][arow] = a_nxt.z;
        As[aoff + 3][arow] = a_nxt.w;
        *(float4*)&Bs[brow    ][bcol] = b_nxt0;
        *(float4*)&Bs[brow + 1][bcol] = b_nxt1;
        __syncthreads();
        if (k0 + 16 < K) {
            a_nxt  = *(const float4*)&A[(size_t)(m0 + arow) * K + k0 + 16 + aoff];
            b_nxt0 = *(const float4*)&B[(size_t)(k0 + 16 + brow    ) * N + n0 + bcol];
            b_nxt1 = *(const float4*)&B[(size_t)(k0 + 16 + brow + 1) * N + n0 + bcol];
        }
#pragma unroll
        for (int kk = 0; kk < 16; kk++) {
            float4 av = *(const float4*)&As[kk][ty * 4];
            ulonglong2 b01 = *(const ulonglong2*)&Bs[kk][tx * 4];        // cols tx*4..+3
            ulonglong2 b23 = *(const ulonglong2*)&Bs[kk][64 + tx * 4];   // cols 64+tx*4..+3
            ull a0 = dup2(av.x), a1 = dup2(av.y), a2 = dup2(av.z), a3 = dup2(av.w);
            c2[0][0] = ffma2(a0, b01.x, c2[0][0]); c2[0][1] = ffma2(a0, b01.y, c2[0][1]);
            c2[0][2] = ffma2(a0, b23.x, c2[0][2]); c2[0][3] = ffma2(a0, b23.y, c2[0][3]);
            c2[1][0] = ffma2(a1, b01.x, c2[1][0]); c2[1][1] = ffma2(a1, b01.y, c2[1][1]);
            c2[1][2] = ffma2(a1, b23.x, c2[1][2]); c2[1][3] = ffma2(a1, b23.y, c2[1][3]);
            c2[2][0] = ffma2(a2, b01.x, c2[2][0]); c2[2][1] = ffma2(a2, b01.y, c2[2][1]);
            c2[2][2] = ffma2(a2, b23.x, c2[2][2]); c2[2][3] = ffma2(a2, b23.y, c2[2][3]);
            c2[3][0] = ffma2(a3, b01.x, c2[3][0]); c2[3][1] = ffma2(a3, b01.y, c2[3][1]);
            c2[3][2] = ffma2(a3, b23.x, c2[3][2]); c2[3][3] = ffma2(a3, b23.y, c2[3][3]);
        }
        __syncthreads();
    }
    int col0 = n0 + tx * 4;
    int col1 = n0 + 64 + tx * 4;
    float4 bb0 = make_float4(0.f, 0.f, 0.f, 0.f);
    float4 bb1 = bb0;
    if (bias) {
        bb0 = *(const float4*)&bias[col0];
        bb1 = *(const float4*)&bias[col1];
    }
#pragma unroll
    for (int i = 0; i < 4; i++) {
        float2 p0 = unpk(c2[i][0]);
        float2 p1 = unpk(c2[i][1]);
        float2 p2 = unpk(c2[i][2]);
        float2 p3 = unpk(c2[i][3]);
        float4 v0 = make_float4(p0.x + bb0.x, p0.y + bb0.y, p1.x + bb0.z, p1.y + bb0.w);
        float4 v1 = make_float4(p2.x + bb1.x, p2.y + bb1.y, p3.x + bb1.z, p3.y + bb1.w);
        float* crow = &C[(size_t)(m0 + ty * 4 + i) * N];
        *(float4*)(crow + col0) = v0;
        *(float4*)(crow + col1) = v1;
    }
}

// ---------------- mb[i] = matrix[i,:] . fc_b ----------------
__global__ void k_mb(const float* __restrict__ matrix, const float* __restrict__ fc_b) {
    int warp = threadIdx.x >> 5, lane = threadIdx.x & 31;
    int i = blockIdx.x * 8 + warp;
    float s = 0.f;
    for (int q = lane; q < QN; q += 32) s = fmaf(matrix[i * QN + q], fc_b[q], s);
#pragma unroll
    for (int o = 16; o; o >>= 1) s += __shfl_down_sync(0xffffffffu, s, o);
    if (lane == 0) g_mb[i] = s;
}

// ---------------- persistent GRU scan (block = 32 j x 8 b) ----------------
// Grid 128 = 16 j-groups x 8 b-groups. w_hh slice (3x32x512 = 198KB) persistent
// in smem, loaded coalesced from row-major w_hh. Per step: stage 8 h-rows
// (16KB) via 4 chunked cp.async groups (each warp stages/consumes its OWN b-row
// -> warp-local wait+syncwarp, no block syncs in the dot). Warp = one b,
// lane = one j: h operand is warp-uniform broadcast, w LDS phase-conflict-free
// (pitch 516), xg/hold/h-write fully coalesced. Grid barrier: red.release +
// ld.acquire polling on a monotonic counter (reset by k_init each launch).
#define WROWS 96
#define WP    516
#define SMEM_W (WROWS * WP)          // 49536 floats
#define SMEM_H (8 * WP)              // 4128 floats
#define GRU_SMEM_BYTES ((SMEM_W + SMEM_H) * 4)   // 214656 B

__global__ void __launch_bounds__(256) k_gru_all(const float* __restrict__ w_hh,
                                                 const float* __restrict__ b_hh) {
    extern __shared__ float smbuf[];
    float* ws = smbuf;             // [96][516]: row g*32+tj = w_hh[g*512 + j0+tj][:]
    float* hs = smbuf + SMEM_W;    // [8][516]:  h_{t-1}[b0+tb][:]
    int tid = threadIdx.x;
    int jg = blockIdx.x >> 3;      // 0..15
    int bg = blockIdx.x & 7;       // 0..7
    int j0 = jg * 32;
    int b0 = bg * 8;

    // stage w once: coalesced float4 from row-major w_hh
    for (int idx = tid; idx < WROWS * 128; idx += 256) {
        int r  = idx >> 7;         // 0..95 = g*32+tj
        int k4 = idx & 127;
        int g = r >> 5, tj = r & 31;
        *(float4*)&ws[r * WP + k4 * 4] =
            *(const float4*)&w_hh[(size_t)(g * HN + j0 + tj) * HN + k4 * 4];
    }

    int tb = tid >> 5;             // warp id = local batch
    int tj = tid & 31;             // lane = local j
    int b = b0 + tb;
    int j = j0 + tj;
    float bhr = b_hh[j], bhz = b_hh[HN + j], bhn = b_hh[2 * HN + j];
    const ulonglong2* wrp = (const ulonglong2*)&ws[(0 * 32 + tj) * WP];
    const ulonglong2* wzp = (const ulonglong2*)&ws[(32 + tj) * WP];
    const ulonglong2* wnp = (const ulonglong2*)&ws[(64 + tj) * WP];
    const ulonglong2* hb  = (const ulonglong2*)&hs[tb * WP];
    unsigned int hs_base = (unsigned int)__cvta_generic_to_shared(hs);
    unsigned int* pbar = &g_bar_count;
    unsigned int bar_target = 0;

    // t=0: zero h staging
    float4 zf = make_float4(0.f, 0.f, 0.f, 0.f);
    for (int idx = tid; idx < 8 * 128; idx += 256) {
        int bb = idx >> 7, k4 = idx & 127;
        *(float4*)&hs[bb * WP + k4 * 4] = zf;
    }
    __syncthreads();

    for (int t = 0; t < LN; t++) {
        // stage h_{t-1}: 4 chunks, 1 cp.async per thread per chunk;
        // warp tb stages its own row (k4 = c*32 + lane)
        if (t > 0) {
            const float* hrow = g_hall + (size_t)(b * LN + (t - 1)) * HN;
#pragma unroll
            for (int c = 0; c < 4; c++) {
                int k4 = c * 32 + tj;
                cpa16(hs_base + (unsigned int)(tb * WP + k4 * 4) * 4u, hrow + k4 * 4);
                asm volatile("cp.async.commit_group;" ::: "memory");
            }
        }

        // xg operands (coalesced 128B per warp per gate)
        int bt = b * LN + t;
        const float* xgp = g_xg + (size_t)bt * G3;
        float xr = xgp[j], xz = xgp[HN + j], xn = xgp[2 * HN + j];

        // chunked dot overlapped with staging (warp-local waits)
        ull r2 = 0ULL, z2 = 0ULL, n2 = 0ULL;
#pragma unroll
        for (int c = 0; c < 4; c++) {
            if (t > 0) {
                if      (c == 0) asm volatile("cp.async.wait_group 3;" ::: "memory");
                else if (c == 1) asm volatile("cp.async.wait_group 2;" ::: "memory");
                else if (c == 2) asm volatile("cp.async.wait_group 1;" ::: "memory");
                else             asm volatile("cp.async.wait_group 0;" ::: "memory");
                __syncwarp();
            }
#pragma unroll 8
            for (int k4 = c * 32; k4 < c * 32 + 32; k4++) {
                ulonglong2 h2  = hb[k4];          // warp-uniform broadcast
                ulonglong2 w_r = wrp[k4];
                ulonglong2 w_z = wzp[k4];
                ulonglong2 w_n = wnp[k4];
                r2 = ffma2(w_r.x, h2.x, r2); r2 = ffma2(w_r.y, h2.y, r2);
                z2 = ffma2(w_z.x, h2.x, z2); z2 = ffma2(w_z.y, h2.y, z2);
                n2 = ffma2(w_n.x, h2.x, n2); n2 = ffma2(w_n.y, h2.y, n2);
            }
        }
        float2 rv = unpk(r2), zv = unpk(z2), nv = unpk(n2);
        float hr = (rv.x + rv.y) + bhr;
        float hz = (zv.x + zv.y) + bhz;
        float hn = (nv.x + nv.y) + bhn;
        float r = 1.f / (1.f + expf(-(xr + hr)));
        float z = 1.f / (1.f + expf(-(xz + hz)));
        float n = tanhf(xn + r * hn);
        float hold = hs[tb * WP + j0 + tj];       // h_{t-1}[b][j], coalesced
        float hnew = (1.f - z) * n + z * hold;
        g_hall[(size_t)bt * HN + j] = hnew;       // coalesced 128B per warp

        // grid barrier (skip after last step)
        if (t + 1 < LN) {
            bar_target += NBLK;
            __syncthreads();          // all warps wrote h, done reading hs
            if (tid == 0) {
                asm volatile("red.release.gpu.global.add.u32 [%0], 1;" :: "l"(pbar) : "memory");
                unsigned int v;
                do {
                    asm volatile("ld.acquire.gpu.global.u32 %0, [%1];" : "=r"(v) : "l"(pbar) : "memory");
                } while (v < bar_target);
            }
            __syncthreads();
        }
    }
}

// ---------------- mval[b,t] = threshold( h[b,t,:] . M2[idx,:] + mb[idx] ) ----------------
__global__ void k_mval() {
    int warp = threadIdx.x >> 5, lane = threadIdx.x & 31;
    int bt = blockIdx.x * 8 + warp;
    int i = g_idx[bt];
    const float* hp = g_hall + (size_t)bt * HN;
    const float* m2 = g_M2 + i * HN;
    float s = 0.f;
#pragma unroll 4
    for (int k = lane; k < HN; k += 32) s = fmaf(hp[k], m2[k], s);
#pragma unroll
    for (int o = 16; o; o >>= 1) s += __shfl_down_sync(0xffffffffu, s, o);
    if (lane == 0) {
        float v = s + g_mb[i];
        g_mval[bt] = (v >= 0.4f) ? 1.0f : v;
    }
}

// ---------------- counters + closed-form DINA -> preds ----------------
__global__ void k_counts(const int* __restrict__ qd) {
    __shared__ int   qs[LN];
    __shared__ float ms[LN];
    __shared__ int   qas[LN];
    __shared__ float a1m[LN], a0m[LN], a0n[LN];
    int b = blockIdx.x;
    int tid = threadIdx.x;
    if (tid < LN) {
        int bt = b * LN + tid;
        int q = qd[bt];
        float m = g_mval[bt];
        int qa = g_qa[bt];
        float mast = (m == 1.0f) ? 1.f : 0.f;
        float notm = (m == 0.0f) ? 1.f : 0.f;
        qs[tid] = q; ms[tid] = m; qas[tid] = qa;
        a1m[tid] = (qa == 1) ? mast : 0.f;
        a0m[tid] = (qa == 0) ? mast : 0.f;
        a0n[tid] = (qa == 0) ? notm : 0.f;
    }
    __syncthreads();
    if (tid < LN) {
        int qt = qs[tid];
        float mc = 0.f, mi = 0.f, nmc = 0.f;
        int cnt = 0;
        float last_gu = 0.f;   // g_upd at latest non-us occurrence
        float last_ss = 0.f;   // mi/aa at latest us occurrence
        for (int k = 0; k < tid; k++) {
            if (qs[k] == qt) {
                float aak = (float)(cnt + 1);
                float mk = ms[k];
                int qak = qas[k];
                bool usk = (mk == 1.0f) && (qak == 0);
                if (usk) {
                    last_ss = mi / aak;
                } else {
                    float gu;
                    if (mk == 1.0f)     gu = mc / aak;
                    else if (qak == 0)  gu = 1.0f - nmc / aak;
                    else                gu = nmc / aak;
                    last_gu = gu;
                }
                mc += a1m[k]; mi += a0m[k]; nmc += a0n[k]; cnt++;
            }
        }
        float aat = (float)(cnt + 1);
        float mt = ms[tid];
        int qat = qas[tid];
        bool ust = (mt == 1.0f) && (qat == 0);
        float ng, ns;
        if (ust) {
            ng = last_gu;
            ns = mi / aat;
        } else {
            if (mt == 1.0f)     ng = mc / aat;
            else if (qat == 0)  ng = 1.0f - nmc / aat;
            else                ng = nmc / aat;
            ns = last_ss;
        }
        float p = (1.f - ns) * (mt * ng + (1.f - ns) * (1.f - mt));
        g_preds[b * LN + tid] = p;
    }
}

// ---------------- final: sigmoid, masked MSE + c_reg, mask count ----------------
__global__ void k_final(const float* __restrict__ target, const int* __restrict__ pidd,
                        const float* __restrict__ diff_parm, float* __restrict__ out,
                        int out_size) {
    __shared__ double sm_[256];
    __shared__ double sc_[256];
    __shared__ int    si_[256];
    int tid = threadIdx.x;
    int poff = (out_size >= BL + 2) ? 1 : 0;
    double mse = 0.0, cr = 0.0;
    int cnt = 0;
    for (int i = tid; i < BL; i += 256) {
        float p = g_preds[i];
        if (poff + i < out_size) out[poff + i] = 1.f / (1.f + expf(-p));
        float lab = target[i];
        if (lab > -0.9f) { double d = (double)p - (double)lab; mse += d * d; cnt++; }
        float pe = diff_parm[pidd[i]];
        cr += (double)pe * (double)pe;
    }
    sm_[tid] = mse; sc_[tid] = cr; si_[tid] = cnt;
    __syncthreads();
    for (int o = 128; o; o >>= 1) {
        if (tid < o) { sm_[tid] += sm_[tid + o]; sc_[tid] += sc_[tid + o]; si_[tid] += si_[tid + o]; }
        __syncthreads();
    }
    if (tid == 0) {
        float loss = (float)(sm_[0] + sc_[0] * 1e-5);
        if (out_size >= BL + 2) {
            out[0] = loss;
            out[BL + 1] = (float)si_[0];
        } else if (out_size == 1) {
            out[0] = loss;
        }
    }
}

// ---------------- launch ----------------
extern "C" void kernel_launch(void* const* d_in, const int* in_sizes, int n_in,
                              void* d_out, int out_size) {
    const int*   qd          = (const int*)  d_in[0];
    const int*   qad         = (const int*)  d_in[1];
    const int*   pidd        = (const int*)  d_in[2];
    const float* matrix      = (const float*)d_in[3];
    const float* target      = (const float*)d_in[4];
    const float* q_emb       = (const float*)d_in[5];
    const float* qa_emb      = (const float*)d_in[6];
    const float* q_emb_diff  = (const float*)d_in[7];
    const float* qa_emb_diff = (const float*)d_in[8];
    const float* diff_parm   = (const float*)d_in[9];
    const float* w_ih        = (const float*)d_in[10];
    const float* w_hh        = (const float*)d_in[11];
    const float* b_ih        = (const float*)d_in[12];
    const float* b_hh        = (const float*)d_in[13];
    const float* fc_w        = (const float*)d_in[14];
    const float* fc_b        = (const float*)d_in[15];
    float* out = (float*)d_out;

    // Device symbol addresses MUST come from cudaGetSymbolAddress — using the
    // symbol name in host code yields the host shadow (ATS silently reads it!).
    float *px, *pxg, *pwihT, *pM2;
    cudaGetSymbolAddress((void**)&px,    g_x);
    cudaGetSymbolAddress((void**)&pxg,   g_xg);
    cudaGetSymbolAddress((void**)&pwihT, g_wihT);
    cudaGetSymbolAddress((void**)&pM2,   g_M2);

    static int smem_set = 0;
    if (!smem_set) {
        cudaFuncSetAttribute(k_gru_all, cudaFuncAttributeMaxDynamicSharedMemorySize,
                             GRU_SMEM_BYTES);
        smem_set = 1;
    }

    k_init<<<1, 32>>>();
    k_transpose<<<256, 256>>>(w_ih);
    k_embed<<<BL, 256>>>(qd, qad, pidd, q_emb, qa_emb, q_emb_diff, qa_emb_diff, diff_parm);

    // xg = x @ w_ih^T + b_ih : M=12800, N=1536, K=512
    k_sgemm<<<dim3(G3 / 128, BL / 64), 256>>>(px, pwihT, b_ih, pxg, BL, G3, TWO_D);
    // M2 = matrix @ fc_w : M=1024, N=512, K=1024
    k_sgemm<<<dim3(HN / 128, QN / 64), 256>>>(matrix, fc_w, nullptr, pM2, QN, HN, QN);
    k_mb<<<128, 256>>>(matrix, fc_b);

    // persistent GRU scan: one launch for all 200 steps
    k_gru_all<<<NBLK, 256, GRU_SMEM_BYTES>>>(w_hh, b_hh);

    k_mval<<<BL / 8, 256>>>();
    k_counts<<<BN, 256>>>(qd);
    k_final<<<1, 256>>>(target, pidd, diff_parm, out, out_size);
}